// round 12
// baseline (speedup 1.0000x reference)
#include <cuda_runtime.h>
#include <cuda_bf16.h>
#include <cuda_fp16.h>
#include <math.h>

#define BB   64
#define TT   256
#define DINN 128
#define UU   1024
#define SEQ  256
#define NB   148
#define NROW (BB*TT)
#define N1   5120       // [W1 | Wr]
#define N2   4096       // Wk
#define KSP  4          // split-K for step GEMMs

// ---------------- device scratch ----------------
__device__ __nv_bfloat16 g_h1pk[(size_t)NROW * UU * 2];   // h1 A-frags (KT=64)
__device__ __nv_bfloat16 g_xpk [(size_t)NROW * UU * 2];   // x  A-frags (KT=64)
__device__ __half g_xh [(size_t)NROW * UU];               // x  fp16 linear
__device__ __half g_keh[(size_t)NROW * UU];               // keys fp16 linear
__device__ __nv_bfloat16 g_Wpk1 [(size_t)UU * N1 * 2];    // B-frags [W1|Wr]
__device__ __nv_bfloat16 g_Wpk2 [(size_t)UU * N2 * 2];    // B-frags Wk
__device__ __nv_bfloat16 g_We2pk[(size_t)UU * UU * 2];
__device__ __nv_bfloat16 g_W2pk [(size_t)UU * UU * 2];
__device__ __nv_bfloat16 g_hpk[BB * UU * 2];              // A-frags h
__device__ __nv_bfloat16 g_cpk[BB * UU * 2];              // A-frags ctx
__device__ float g_qp[KSP][BB][N1];                       // split-K partials
__device__ float g_zp[KSP][BB][N2];
__device__ float g_c [BB * UU];
__device__ float g_sc[BB * TT];
__device__ unsigned g_bar_cnt = 0;
__device__ unsigned g_bar_gen = 0;
__device__ unsigned g_ctr[6];

// ---------------- helpers ----------------
__device__ __forceinline__ float tanh_hw(float x) {
    float y; asm("tanh.approx.f32 %0, %1;" : "=f"(y) : "f"(x)); return y;
}
__device__ __forceinline__ float fast_tanh(float x) {
    float e = __expf(2.0f * x);
    return 1.0f - __fdividef(2.0f, e + 1.0f);
}
__device__ __forceinline__ float sigf(float x) {
    return __fdividef(1.0f, 1.0f + __expf(-x));
}
__device__ __forceinline__ void mma16816(float d[4], const uint4& a, const uint2& b) {
    asm("mma.sync.aligned.m16n8k16.row.col.f32.bf16.bf16.f32 "
        "{%0,%1,%2,%3},{%4,%5,%6,%7},{%8,%9},{%0,%1,%2,%3};"
        : "+f"(d[0]), "+f"(d[1]), "+f"(d[2]), "+f"(d[3])
        : "r"(a.x), "r"(a.y), "r"(a.z), "r"(a.w), "r"(b.x), "r"(b.y));
}
__device__ __forceinline__ void cp16(void* smem, const void* g) {
    unsigned s = (unsigned)__cvta_generic_to_shared(smem);
    asm volatile("cp.async.cg.shared.global [%0], [%1], 16;" :: "r"(s), "l"(g));
}
__device__ __forceinline__ void cp_commit() {
    asm volatile("cp.async.commit_group;");
}
template<int N> __device__ __forceinline__ void cp_wait() {
    asm volatile("cp.async.wait_group %0;" :: "n"(N));
}

// grid barrier with counter reset: releaser resets g_ctr[rst] before release
__device__ __forceinline__ void grid_bar(int rst) {
    __syncthreads();
    if (threadIdx.x == 0) {
        unsigned gen;
        asm volatile("ld.acquire.gpu.u32 %0, [%1];" : "=r"(gen) : "l"(&g_bar_gen));
        unsigned prev;
        asm volatile("atom.acq_rel.gpu.add.u32 %0, [%1], 1;"
                     : "=r"(prev) : "l"(&g_bar_cnt));
        if (prev == NB - 1) {
            asm volatile("st.relaxed.gpu.u32 [%0], 0;" :: "l"(&g_ctr[rst]));
            asm volatile("st.relaxed.gpu.u32 [%0], 0;" :: "l"(&g_bar_cnt));
            unsigned d;
            asm volatile("atom.add.release.gpu.u32 %0, [%1], 1;"
                         : "=r"(d) : "l"(&g_bar_gen));
        } else {
            unsigned g;
            do {
                __nanosleep(64);
                asm volatile("ld.acquire.gpu.u32 %0, [%1];" : "=r"(g) : "l"(&g_bar_gen));
            } while (g == gen);
        }
    }
    __syncthreads();
}

// ---------------- split + A-fragment pack (kt stride = ktot) ----------------
__device__ __forceinline__ void split_bf16(float v, __nv_bfloat16& hi, __nv_bfloat16& lo) {
    hi = __float2bfloat16(v);
    lo = __float2bfloat16(v - __bfloat162float(hi));
}
__device__ __forceinline__ void pack_a(__nv_bfloat16* dst, int row, int u,
                                       float vx, float vy, int ktot)
{
    const int mt = row >> 4, rm = row & 15;
    const int kt = u >> 4,  cm = u & 15;          // u even
    const int lane = (rm & 7) * 4 + ((cm & 7) >> 1);
    const int reg  = (rm >> 3) + ((cm >> 3) & 1) * 2;
    const size_t base = ((size_t)(mt * ktot + kt) * 32 + lane) * 16;
    __nv_bfloat16 hx, lx, hy, ly;
    split_bf16(vx, hx, lx);
    split_bf16(vy, hy, ly);
    __nv_bfloat162 hp; hp.x = hx; hp.y = hy;
    __nv_bfloat162 lp; lp.x = lx; lp.y = ly;
    *(__nv_bfloat162*)&dst[base + reg * 2]     = hp;
    *(__nv_bfloat162*)&dst[base + 8 + reg * 2] = lp;
}

// ---------------- GEMM1 (fp32 SIMT, K=128): h1pk = pack(relu(inputs@We1+be1)) ----
__global__ __launch_bounds__(256, 2)
void sgemm128_pack(const float* __restrict__ A, const float* __restrict__ Bm,
                   const float* __restrict__ bias, int N, int K)
{
    __shared__ float As[8][128];
    __shared__ float Bs[8][128];
    const int tid  = threadIdx.x;
    const int brow = blockIdx.y, bcol = blockIdx.x;
    const int tr = tid >> 4, tc = tid & 15;
    const int aRow = tid >> 1, aCol = (tid & 1) * 4;
    const int bRow = tid >> 5, bCol = (tid & 31) * 4;
    const float* Ap = A + (size_t)(brow * 128) * K;
    const float* Bp = Bm + bcol * 128;

    float acc[8][8];
#pragma unroll
    for (int i = 0; i < 8; i++)
#pragma unroll
        for (int j = 0; j < 8; j++) acc[i][j] = 0.f;

    for (int k0 = 0; k0 < K; k0 += 8) {
        float4 av = *(const float4*)(Ap + (size_t)aRow * K + k0 + aCol);
        As[aCol + 0][aRow] = av.x; As[aCol + 1][aRow] = av.y;
        As[aCol + 2][aRow] = av.z; As[aCol + 3][aRow] = av.w;
        float4 bv = *(const float4*)(Bp + (size_t)(k0 + bRow) * N + bCol);
        *(float4*)&Bs[bRow][bCol] = bv;
        __syncthreads();
#pragma unroll
        for (int kk = 0; kk < 8; kk++) {
            float4 a0 = *(const float4*)&As[kk][tr * 8];
            float4 a1 = *(const float4*)&As[kk][tr * 8 + 4];
            float4 b0 = *(const float4*)&Bs[kk][tc * 8];
            float4 b1 = *(const float4*)&Bs[kk][tc * 8 + 4];
            float ar[8] = {a0.x,a0.y,a0.z,a0.w,a1.x,a1.y,a1.z,a1.w};
            float br[8] = {b0.x,b0.y,b0.z,b0.w,b1.x,b1.y,b1.z,b1.w};
#pragma unroll
            for (int i = 0; i < 8; i++)
#pragma unroll
                for (int j = 0; j < 8; j++)
                    acc[i][j] = fmaf(ar[i], br[j], acc[i][j]);
        }
        __syncthreads();
    }
#pragma unroll
    for (int i = 0; i < 8; i++) {
        int row = brow * 128 + tr * 8 + i;
#pragma unroll
        for (int j = 0; j < 8; j += 2) {
            int col = bcol * 128 + tc * 8 + j;
            float v0 = fmaxf(acc[i][j]     + bias[col],     0.f);
            float v1 = fmaxf(acc[i][j + 1] + bias[col + 1], 0.f);
            pack_a(g_h1pk, row, col, v0, v1, 64);
        }
    }
}

// ---------------- pack weights into split B-fragment layout ----------------
__global__ void pack_weights(const float* __restrict__ W1, const float* __restrict__ Wr,
                             const float* __restrict__ Wk, const float* __restrict__ We2,
                             const float* __restrict__ W2)
{
    const int TOT1 = (N1 / 8) * 64 * 32;
    const int TOT2 = (N2 / 8) * 64 * 32;
    const int TOT3 = (UU / 8) * 64 * 32;
    int c = blockIdx.x * blockDim.x + threadIdx.x;
    float w[4];
    __nv_bfloat16* o;
    if (c < TOT1) {
        int cl = c;
        int nt8 = cl / 2048, rem = cl % 2048, kt = rem >> 5, l = rem & 31;
        int n  = nt8 * 8 + (l >> 2);
        int k0 = kt * 16 + (l & 3) * 2;
        const float* W; int ld, nn;
        if (n < 1024) { W = W1; ld = 1024; nn = n; }
        else          { W = Wr; ld = 4096; nn = n - 1024; }
        w[0] = W[(size_t)(k0    ) * ld + nn];
        w[1] = W[(size_t)(k0 + 1) * ld + nn];
        w[2] = W[(size_t)(k0 + 8) * ld + nn];
        w[3] = W[(size_t)(k0 + 9) * ld + nn];
        o = g_Wpk1 + (size_t)cl * 8;
    } else if (c < TOT1 + TOT2) {
        int cl = c - TOT1;
        int nt8 = cl / 2048, rem = cl % 2048, kt = rem >> 5, l = rem & 31;
        int n  = nt8 * 8 + (l >> 2);
        int k0 = kt * 16 + (l & 3) * 2;
        w[0] = Wk[(size_t)(k0    ) * 4096 + n];
        w[1] = Wk[(size_t)(k0 + 1) * 4096 + n];
        w[2] = Wk[(size_t)(k0 + 8) * 4096 + n];
        w[3] = Wk[(size_t)(k0 + 9) * 4096 + n];
        o = g_Wpk2 + (size_t)cl * 8;
    } else if (c < TOT1 + TOT2 + 2 * TOT3) {
        int cl = c - TOT1 - TOT2;
        const float* W = We2;
        __nv_bfloat16* dst = g_We2pk;
        if (cl >= TOT3) { cl -= TOT3; W = W2; dst = g_W2pk; }
        int nt8 = cl / 2048, rem = cl % 2048, kt = rem >> 5, l = rem & 31;
        int n  = nt8 * 8 + (l >> 2);
        int k0 = kt * 16 + (l & 3) * 2;
        w[0] = W[(size_t)(k0    ) * 1024 + n];
        w[1] = W[(size_t)(k0 + 1) * 1024 + n];
        w[2] = W[(size_t)(k0 + 8) * 1024 + n];
        w[3] = W[(size_t)(k0 + 9) * 1024 + n];
        o = dst + (size_t)cl * 8;
    } else return;
#pragma unroll
    for (int i = 0; i < 4; i++) split_bf16(w[i], o[i], o[4 + i]);
}

// ---------------- big split-bf16 HMMA (precompute) ----------------
__global__ __launch_bounds__(256)
void hgemm_big(const __nv_bfloat16* __restrict__ Apk,
               const __nv_bfloat16* __restrict__ Wpk,
               const float* __restrict__ bias, int doRelu, int N,
               __nv_bfloat16* __restrict__ outPk, __half* __restrict__ outH)
{
    const int tiles_n = N / 32;
    const int tm = blockIdx.x / tiles_n, tn = blockIdx.x % tiles_n;
    const int tid = threadIdx.x;
    const int w = tid >> 5, l = tid & 31;
    const int mt = w >> 1, np = w & 1;
    const int mtg = tm * 4 + mt;
    const uint4* a_it  = (const uint4*)Apk + ((size_t)mtg * 2048 + l) * 2;
    const int nt0 = tn * 4 + np * 2;
    const uint4* b0_it = (const uint4*)Wpk + (size_t)nt0 * 2048 + l;
    const uint4* b1_it = b0_it + 2048;

    float d0[4] = {0.f,0.f,0.f,0.f};
    float d1[4] = {0.f,0.f,0.f,0.f};
#pragma unroll 4
    for (int kt = 0; kt < 64; kt++) {
        uint4 aH = a_it[(size_t)kt * 64];
        uint4 aL = a_it[(size_t)kt * 64 + 1];
        uint4 b0 = b0_it[kt * 32];
        uint4 b1 = b1_it[kt * 32];
        uint2 b0H = make_uint2(b0.x, b0.y), b0L = make_uint2(b0.z, b0.w);
        uint2 b1H = make_uint2(b1.x, b1.y), b1L = make_uint2(b1.z, b1.w);
        mma16816(d0, aH, b0H);
        mma16816(d0, aH, b0L);
        mma16816(d0, aL, b0H);
        mma16816(d1, aH, b1H);
        mma16816(d1, aH, b1L);
        mma16816(d1, aL, b1H);
    }
    const int r0 = tm * 64 + mt * 16 + (l >> 2);
    const int c0 = tn * 32 + np * 16 + ((l & 3) << 1);
    float2 bbA = *(const float2*)&bias[c0];
    float2 bbB = *(const float2*)&bias[c0 + 8];
    d0[0] += bbA.x; d0[1] += bbA.y; d0[2] += bbA.x; d0[3] += bbA.y;
    d1[0] += bbB.x; d1[1] += bbB.y; d1[2] += bbB.x; d1[3] += bbB.y;
    if (doRelu) {
#pragma unroll
        for (int i = 0; i < 4; i++) {
            d0[i] = fmaxf(d0[i], 0.f);
            d1[i] = fmaxf(d1[i], 0.f);
        }
    }
    if (outH) {
        *(__half2*)&outH[(size_t)r0 * N + c0]           = __floats2half2_rn(d0[0], d0[1]);
        *(__half2*)&outH[(size_t)(r0 + 8) * N + c0]     = __floats2half2_rn(d0[2], d0[3]);
        *(__half2*)&outH[(size_t)r0 * N + c0 + 8]       = __floats2half2_rn(d1[0], d1[1]);
        *(__half2*)&outH[(size_t)(r0 + 8) * N + c0 + 8] = __floats2half2_rn(d1[2], d1[3]);
    }
    if (outPk) {
        pack_a(outPk, r0,     c0,     d0[0], d0[1], 64);
        pack_a(outPk, r0 + 8, c0,     d0[2], d0[3], 64);
        pack_a(outPk, r0,     c0 + 8, d1[0], d1[1], 64);
        pack_a(outPk, r0 + 8, c0 + 8, d1[2], d1[3], 64);
    }
}

// ---------------- init ----------------
__global__ void init_state(float* __restrict__ out)
{
    int idx = blockIdx.x * blockDim.x + threadIdx.x;
    if (idx < BB * UU) g_c[idx] = 0.f;
    if (idx < BB * UU * 2) g_hpk[idx] = __float2bfloat16(0.f);
    if (idx < SEQ * BB) out[idx] = 0.f;
    if (idx == 0) {
        g_bar_cnt = 0;
        for (int i = 0; i < 6; i++) g_ctr[i] = 0;
    }
}

// ---------------- smem-staged 64x(16*NJ) GEMM task, NC k128-chunks ----------
template<int NJ, int NC>
__device__ __forceinline__ void gtile(const uint4* __restrict__ Apk, int ktaTot, int ktA0,
                                      const uint4* __restrict__ Wpk, int ktbTot, int ktB0,
                                      float* __restrict__ C, int ldc, int n0,
                                      uint4* sA, uint4* sB)
{
    constexpr int NT = 2 * NJ;
    const int tid = threadIdx.x;
    const int w = tid >> 5, l = tid & 31;
    const int mt = w >> 1, np = w & 1;
    const int nt8base = n0 >> 3;

    float d[NJ][4];
#pragma unroll
    for (int j = 0; j < NJ; j++)
#pragma unroll
        for (int i = 0; i < 4; i++) d[j][i] = 0.f;

    auto load = [&](int buf, int cix) {
        const int ka = ktA0 + cix * 8;
        const int kb = ktB0 + cix * 8;
#pragma unroll
        for (int i = tid; i < 1024; i += 256) {
            int lane = i & 31, mtt = (i >> 5) & 3, ktl = i >> 7;
            const uint4* src = Apk + ((size_t)(mtt * ktaTot + ka + ktl) * 32 + lane) * 2;
            cp16(&sA[(((buf * 2 + 0) * 8 + ktl) * 4 + mtt) * 32 + lane], src);
            cp16(&sA[(((buf * 2 + 1) * 8 + ktl) * 4 + mtt) * 32 + lane], src + 1);
        }
        for (int i = tid; i < NT * 8 * 32; i += 256) {
            int lane = i & 31, nt = (i >> 5) % NT, ktl = (i >> 5) / NT;
            const uint4* src = Wpk + (size_t)((nt8base + nt) * ktbTot + kb + ktl) * 32 + lane;
            cp16(&sB[((buf * 8 + ktl) * NT + nt) * 32 + lane], src);
        }
        cp_commit();
    };

    load(0, 0);
    for (int c = 0; c < NC; c++) {
        if (c < NC - 1) { load((c + 1) & 1, c + 1); cp_wait<1>(); }
        else            { cp_wait<0>(); }
        __syncthreads();
        const int buf = c & 1;
#pragma unroll
        for (int ktl = 0; ktl < 8; ktl++) {
            uint4 aH = sA[(((buf * 2 + 0) * 8 + ktl) * 4 + mt) * 32 + l];
            uint4 aL = sA[(((buf * 2 + 1) * 8 + ktl) * 4 + mt) * 32 + l];
#pragma unroll
            for (int j = 0; j < NJ; j++) {
                uint4 b = sB[((buf * 8 + ktl) * NT + np * NJ + j) * 32 + l];
                uint2 bH = make_uint2(b.x, b.y), bL = make_uint2(b.z, b.w);
                mma16816(d[j], aH, bH);
                mma16816(d[j], aH, bL);
                mma16816(d[j], aL, bH);
            }
        }
        __syncthreads();
    }
    const int r0 = mt * 16 + (l >> 2);
#pragma unroll
    for (int j = 0; j < NJ; j++) {
        const int c0 = n0 + (np * NJ + j) * 8 + ((l & 3) << 1);
        *(float2*)&C[(size_t)r0 * ldc + c0]       = make_float2(d[j][0], d[j][1]);
        *(float2*)&C[(size_t)(r0 + 8) * ldc + c0] = make_float2(d[j][2], d[j][3]);
    }
}

// fetch one task id via thread0 + smem broadcast
#define FETCH_TASK(pidx, lim, tvar)                                        \
    __syncthreads();                                                       \
    if (tid == 0) s_task = atomicAdd(&g_ctr[pidx], 1u);                    \
    __syncthreads();                                                       \
    tvar = s_task;                                                         \
    if (tvar >= (lim)) break;

// ---------------- persistent decode (dynamic work-stealing phases) --------
extern __shared__ uint4 dynsm[];
__global__ __launch_bounds__(256, 1)
void decode_persistent(const float* __restrict__ b1, const float* __restrict__ V,
                       const float* __restrict__ bl, const float* __restrict__ Wo,
                       const float* __restrict__ bo, float* __restrict__ out)
{
    __shared__ float sp[256];
    __shared__ float red[8];
    __shared__ unsigned s_task;
    uint4* sA = dynsm;          // 64 KB
    uint4* sB = dynsm + 4096;   // 64 KB
    float* fsm = (float*)dynsm; // scratch reuse in ctx phase
    const int tid  = threadIdx.x;
    const int bid  = blockIdx.x;
    const int warp = tid >> 5, lane = tid & 31;

    for (int s = 0; s < SEQ; s++) {
        // ---- P1: qp[kh] = h @ [W1|Wr]  (320 tasks: 80 n-tiles x 4 k-quarters) ----
        for (;;) {
            unsigned t;
            FETCH_TASK(0, 320u, t);
            const int nt = (int)(t % 80u), kh = (int)(t / 80u);
            gtile<4, 2>((const uint4*)g_hpk, 64, kh * 16,
                        (const uint4*)g_Wpk1, 64, kh * 16,
                        &g_qp[kh][0][0], N1, nt * 64, sA, sB);
        }
        grid_bar(0);

        // ---- P2: scores (256 tasks: b x t-quarter) ----
        for (;;) {
            unsigned t;
            FETCH_TASK(1, 256u, t);
            const int b = (int)(t >> 2), tq = (int)(t & 3u);
            float qr[32], vr[32];
#pragma unroll
            for (int it = 0; it < 4; it++) {
                const int base = it * 256 + lane * 8;
#pragma unroll
                for (int k2 = 0; k2 < 8; k2 += 4) {
                    float4 q0 = *(const float4*)&g_qp[0][b][base + k2];
                    float4 q1 = *(const float4*)&g_qp[1][b][base + k2];
                    float4 q2 = *(const float4*)&g_qp[2][b][base + k2];
                    float4 q3 = *(const float4*)&g_qp[3][b][base + k2];
                    float4 bb = *(const float4*)&b1[base + k2];
                    float4 vv = *(const float4*)&V[base + k2];
                    qr[it*8+k2+0] = q0.x + q1.x + q2.x + q3.x + bb.x;  vr[it*8+k2+0] = vv.x;
                    qr[it*8+k2+1] = q0.y + q1.y + q2.y + q3.y + bb.y;  vr[it*8+k2+1] = vv.y;
                    qr[it*8+k2+2] = q0.z + q1.z + q2.z + q3.z + bb.z;  vr[it*8+k2+2] = vv.z;
                    qr[it*8+k2+3] = q0.w + q1.w + q2.w + q3.w + bb.w;  vr[it*8+k2+3] = vv.w;
                }
            }
            for (int tl = warp; tl < 64; tl += 8) {
                const int tt = tq * 64 + tl;
                const uint4* kp = (const uint4*)(g_keh + ((size_t)(b * 256 + tt)) * 1024);
                float s0 = 0.f;
#pragma unroll
                for (int it = 0; it < 4; it++) {
                    uint4 kv = kp[it * 32 + lane];
                    float2 f0 = __half22float2(*(__half2*)&kv.x);
                    float2 f1 = __half22float2(*(__half2*)&kv.y);
                    float2 f2 = __half22float2(*(__half2*)&kv.z);
                    float2 f3 = __half22float2(*(__half2*)&kv.w);
                    s0 += vr[it*8+0] * tanh_hw(qr[it*8+0] + f0.x);
                    s0 += vr[it*8+1] * tanh_hw(qr[it*8+1] + f0.y);
                    s0 += vr[it*8+2] * tanh_hw(qr[it*8+2] + f1.x);
                    s0 += vr[it*8+3] * tanh_hw(qr[it*8+3] + f1.y);
                    s0 += vr[it*8+4] * tanh_hw(qr[it*8+4] + f2.x);
                    s0 += vr[it*8+5] * tanh_hw(qr[it*8+5] + f2.y);
                    s0 += vr[it*8+6] * tanh_hw(qr[it*8+6] + f3.x);
                    s0 += vr[it*8+7] * tanh_hw(qr[it*8+7] + f3.y);
                }
#pragma unroll
                for (int o = 16; o; o >>= 1) s0 += __shfl_xor_sync(0xffffffffu, s0, o);
                if (!lane) g_sc[b * 256 + tt] = s0;
            }
        }
        grid_bar(1);

        // ---- P3: softmax + ctx (256 tasks: b x u-quarter; t split over 2 thread-halves) ----
        for (;;) {
            unsigned t;
            FETCH_TASK(2, 256u, t);
            const int b = (int)(t >> 2), uq = (int)(t & 3u);
            // softmax over 256 scores of b
            float v = g_sc[b * 256 + tid];
            float m = v;
#pragma unroll
            for (int o = 16; o; o >>= 1) m = fmaxf(m, __shfl_xor_sync(0xffffffffu, m, o));
            if (!lane) red[warp] = m;
            __syncthreads();
            float bm = red[0];
#pragma unroll
            for (int w2 = 1; w2 < 8; w2++) bm = fmaxf(bm, red[w2]);
            __syncthreads();
            float e = __expf(v - bm);
            float ss = e;
#pragma unroll
            for (int o = 16; o; o >>= 1) ss += __shfl_xor_sync(0xffffffffu, ss, o);
            if (!lane) red[warp] = ss;
            __syncthreads();
            float bs = 0.f;
#pragma unroll
            for (int w2 = 0; w2 < 8; w2++) bs += red[w2];
            sp[tid] = __fdividef(e, bs);
            __syncthreads();

            // ctx: 256 cols; thread (cidx, th): col pair u0, t-half th
            const int cidx = tid & 127, th = tid >> 7;
            const int u0 = uq * 256 + cidx * 2;
            const __half2* xb = (const __half2*)(g_xh + (size_t)b * 256 * 1024 + u0);
            float ax = 0.f, ay = 0.f;
            const int tbeg = th * 128;
#pragma unroll 8
            for (int t2 = tbeg; t2 < tbeg + 128; t2++) {
                float2 xv = __half22float2(xb[(size_t)t2 * 512]);
                float wt = sp[t2];
                ax = fmaf(wt, xv.x, ax);
                ay = fmaf(wt, xv.y, ay);
            }
            fsm[tid] = ax; fsm[256 + tid] = ay;
            __syncthreads();
            if (tid < 128) {
                ax = fsm[tid] + fsm[tid + 128];
                ay = fsm[256 + tid] + fsm[256 + tid + 128];
                pack_a(g_cpk, b, u0, ax, ay, 64);
            }
        }
        grid_bar(2);

        // ---- P4: zp[kh] = ctx @ Wk  (256 tasks: 64 n-tiles x 4 k-quarters) ----
        for (;;) {
            unsigned t;
            FETCH_TASK(3, 256u, t);
            const int nt = (int)(t & 63u), kh = (int)(t >> 6);
            gtile<4, 2>((const uint4*)g_cpk, 64, kh * 16,
                        (const uint4*)g_Wpk2, 64, kh * 16,
                        &g_zp[kh][0][0], N2, nt * 64, sA, sB);
        }
        grid_bar(3);

        // ---- P5: LSTM gates + state + projection (static, 128 blocks) ----
        if (bid < 128) {
            const int b2 = bid >> 1, jhalf = bid & 1;
            const int j0 = jhalf * 512 + tid * 2;
            float zx[4], zy[4];
#pragma unroll
            for (int g = 0; g < 4; g++) {
                zx[g] = bl[g * 1024 + j0];
                zy[g] = bl[g * 1024 + j0 + 1];
#pragma unroll
                for (int kh = 0; kh < KSP; kh++) {
                    float2 a = *(const float2*)&g_zp[kh][b2][g * 1024 + j0];
                    float2 c = *(const float2*)&g_qp[kh][b2][1024 + g * 1024 + j0];
                    zx[g] += a.x + c.x;
                    zy[g] += a.y + c.y;
                }
            }
            float2 cold = *(const float2*)&g_c[b2 * 1024 + j0];
            float cx = sigf(zx[1]) * cold.x + sigf(zx[0]) * fast_tanh(zx[2]);
            float cy = sigf(zy[1]) * cold.y + sigf(zy[0]) * fast_tanh(zy[2]);
            float hx = sigf(zx[3]) * fast_tanh(cx);
            float hy = sigf(zy[3]) * fast_tanh(cy);
            *(float2*)&g_c[b2 * 1024 + j0] = make_float2(cx, cy);
            pack_a(g_hpk, b2, j0, hx, hy, 64);

            float p = hx * Wo[j0] + hy * Wo[j0 + 1];
            if (tid == 0 && jhalf == 0) p += bo[0];
#pragma unroll
            for (int o = 16; o; o >>= 1) p += __shfl_xor_sync(0xffffffffu, p, o);
            if (!lane) red[warp] = p;
            __syncthreads();
            if (tid == 0) {
                float acc = 0.f;
#pragma unroll
                for (int w2 = 0; w2 < 8; w2++) acc += red[w2];
                atomicAdd(&out[s * 64 + b2], acc);
            }
            __syncthreads();
        }
        grid_bar(4);
    }
}

// ---------------- host launcher ----------------
extern "C" void kernel_launch(void* const* d_in, const int* in_sizes, int n_in,
                              void* d_out, int out_size)
{
    const float* inputs = (const float*)d_in[0];
    const float* We1 = (const float*)d_in[1];  const float* be1 = (const float*)d_in[2];
    const float* We2 = (const float*)d_in[3];  const float* be2 = (const float*)d_in[4];
    const float* W1  = (const float*)d_in[5];  const float* b1  = (const float*)d_in[6];
    const float* W2  = (const float*)d_in[7];  const float* b2k = (const float*)d_in[8];
    const float* V   = (const float*)d_in[9];  /* bV shift-invariant in softmax */
    const float* Wk  = (const float*)d_in[11]; const float* Wr  = (const float*)d_in[12];
    const float* bl  = (const float*)d_in[13]; const float* Wo  = (const float*)d_in[14];
    const float* bo  = (const float*)d_in[15];
    float* out = (float*)d_out;

    void *p_h1pk, *p_xpk, *p_xh, *p_keh, *p_We2pk, *p_W2pk;
    cudaGetSymbolAddress(&p_h1pk,  g_h1pk);
    cudaGetSymbolAddress(&p_xpk,   g_xpk);
    cudaGetSymbolAddress(&p_xh,    g_xh);
    cudaGetSymbolAddress(&p_keh,   g_keh);
    cudaGetSymbolAddress(&p_We2pk, g_We2pk);
    cudaGetSymbolAddress(&p_W2pk,  g_W2pk);

    const int DYN_SMEM = (4096 + 4096) * 16;   // 128 KB
    static int attr_set = 0;
    if (!attr_set) {
        cudaFuncSetAttribute(decode_persistent,
                             cudaFuncAttributeMaxDynamicSharedMemorySize, DYN_SMEM);
        attr_set = 1;
    }

    pack_weights<<<5632, 512>>>(W1, Wr, Wk, We2, W2);
    sgemm128_pack<<<dim3(UU / 128, NROW / 128), 256>>>(inputs, We1, be1, UU, DINN);
    hgemm_big<<<(NROW / 64) * (UU / 32), 256>>>(
        (const __nv_bfloat16*)p_h1pk, (const __nv_bfloat16*)p_We2pk, be2, 1, UU,
        (__nv_bfloat16*)p_xpk, (__half*)p_xh);
    hgemm_big<<<(NROW / 64) * (UU / 32), 256>>>(
        (const __nv_bfloat16*)p_xpk, (const __nv_bfloat16*)p_W2pk, b2k, 0, UU,
        (__nv_bfloat16*)0, (__half*)p_keh);
    init_state<<<128, 1024>>>(out);
    decode_persistent<<<NB, 256, DYN_SMEM>>>(b1, V, bl, Wo, bo, out);
}

// round 13
// speedup vs baseline: 1.1170x; 1.1170x over previous
#include <cuda_runtime.h>
#include <cuda_bf16.h>
#include <cuda_fp16.h>
#include <math.h>

#define BB   64
#define TT   256
#define DINN 128
#define UU   1024
#define SEQ  256
#define NROW (BB*TT)
#define NB   128
#define N1   5120       // [W1 | Wr]
#define N2   4096       // Wk

// ---------------- device scratch ----------------
__device__ __nv_bfloat16 g_h1pk[(size_t)NROW * UU * 2];   // h1 A-frags (KT=64)
__device__ __nv_bfloat16 g_xpk [(size_t)NROW * UU * 2];   // x  A-frags (KT=64)
__device__ __half g_xh [(size_t)NROW * UU];               // x  fp16 linear
__device__ __half g_keh[(size_t)NROW * UU];               // keys fp16 linear
__device__ __nv_bfloat16 g_Wpk1 [(size_t)UU * N1 * 2];    // B-frags [W1|Wr]
__device__ __nv_bfloat16 g_Wpk2 [(size_t)UU * N2 * 2];    // B-frags Wk
__device__ __nv_bfloat16 g_We2pk[(size_t)UU * UU * 2];
__device__ __nv_bfloat16 g_W2pk [(size_t)UU * UU * 2];
__device__ __nv_bfloat16 g_hpk[BB * UU * 2];              // A-frags h
__device__ __nv_bfloat16 g_cpk[BB * UU * 2];              // A-frags ctx
__device__ float g_qp[2][BB][N1];                         // split-K partials
__device__ float g_zp[2][BB][N2];
__device__ float g_c [BB * UU];
__device__ float g_sc[BB * TT];
// hierarchical barrier state (group counters padded to 128B lines)
__device__ unsigned g_grp[16 * 32];
__device__ unsigned g_root    = 0;
__device__ unsigned g_bar_gen = 0;

// ---------------- helpers ----------------
__device__ __forceinline__ float tanh_hw(float x) {
    float y; asm("tanh.approx.f32 %0, %1;" : "=f"(y) : "f"(x)); return y;
}
__device__ __forceinline__ float fast_tanh(float x) {
    float e = __expf(2.0f * x);
    return 1.0f - __fdividef(2.0f, e + 1.0f);
}
__device__ __forceinline__ float sigf(float x) {
    return __fdividef(1.0f, 1.0f + __expf(-x));
}
__device__ __forceinline__ void mma16816(float d[4], const uint4& a, const uint2& b) {
    asm("mma.sync.aligned.m16n8k16.row.col.f32.bf16.bf16.f32 "
        "{%0,%1,%2,%3},{%4,%5,%6,%7},{%8,%9},{%0,%1,%2,%3};"
        : "+f"(d[0]), "+f"(d[1]), "+f"(d[2]), "+f"(d[3])
        : "r"(a.x), "r"(a.y), "r"(a.z), "r"(a.w), "r"(b.x), "r"(b.y));
}
__device__ __forceinline__ void cp16(void* smem, const void* g) {
    unsigned s = (unsigned)__cvta_generic_to_shared(smem);
    asm volatile("cp.async.cg.shared.global [%0], [%1], 16;" :: "r"(s), "l"(g));
}
__device__ __forceinline__ void cp_commit() {
    asm volatile("cp.async.commit_group;");
}
template<int N> __device__ __forceinline__ void cp_wait() {
    asm volatile("cp.async.wait_group %0;" :: "n"(N));
}

// two-level grid barrier: 16 groups x 8 arrivals -> root of 16; nanosleep spin
__device__ __forceinline__ void grid_bar() {
    __syncthreads();
    if (threadIdx.x == 0) {
        unsigned gen;
        asm volatile("ld.acquire.gpu.u32 %0, [%1];" : "=r"(gen) : "l"(&g_bar_gen));
        unsigned* gc = &g_grp[(blockIdx.x >> 3) * 32];
        unsigned prev;
        asm volatile("atom.acq_rel.gpu.add.u32 %0, [%1], 1;" : "=r"(prev) : "l"(gc));
        bool released = false;
        if (prev == 7) {   // last of group -> arrive at root
            unsigned p2;
            asm volatile("atom.acq_rel.gpu.add.u32 %0, [%1], 1;"
                         : "=r"(p2) : "l"(&g_root));
            if (p2 == 15) { // last overall -> reset counters, release
#pragma unroll
                for (int g = 0; g < 16; g++)
                    asm volatile("st.relaxed.gpu.u32 [%0], 0;" :: "l"(&g_grp[g * 32]));
                asm volatile("st.relaxed.gpu.u32 [%0], 0;" :: "l"(&g_root));
                unsigned d;
                asm volatile("atom.add.release.gpu.u32 %0, [%1], 1;"
                             : "=r"(d) : "l"(&g_bar_gen));
                released = true;
            }
        }
        if (!released) {
            unsigned g;
            do {
                __nanosleep(128);
                asm volatile("ld.acquire.gpu.u32 %0, [%1];" : "=r"(g) : "l"(&g_bar_gen));
            } while (g == gen);
        }
    }
    __syncthreads();
}

// ---------------- split + A-fragment pack ----------------
__device__ __forceinline__ void split_bf16(float v, __nv_bfloat16& hi, __nv_bfloat16& lo) {
    hi = __float2bfloat16(v);
    lo = __float2bfloat16(v - __bfloat162float(hi));
}
__device__ __forceinline__ void pack_a(__nv_bfloat16* dst, int row, int u,
                                       float vx, float vy)
{
    const int mt = row >> 4, rm = row & 15;
    const int kt = u >> 4,  cm = u & 15;          // u even
    const int lane = (rm & 7) * 4 + ((cm & 7) >> 1);
    const int reg  = (rm >> 3) + ((cm >> 3) & 1) * 2;
    const size_t base = ((size_t)(mt * 64 + kt) * 32 + lane) * 16;
    __nv_bfloat16 hx, lx, hy, ly;
    split_bf16(vx, hx, lx);
    split_bf16(vy, hy, ly);
    __nv_bfloat162 hp; hp.x = hx; hp.y = hy;
    __nv_bfloat162 lp; lp.x = lx; lp.y = ly;
    *(__nv_bfloat162*)&dst[base + reg * 2]     = hp;
    *(__nv_bfloat162*)&dst[base + 8 + reg * 2] = lp;
}

// ---------------- GEMM1 (fp32 SIMT, K=128): h1pk = pack(relu(inputs@We1+be1)) ----
__global__ __launch_bounds__(256, 2)
void sgemm128_pack(const float* __restrict__ A, const float* __restrict__ Bm,
                   const float* __restrict__ bias, int N, int K)
{
    __shared__ float As[8][128];
    __shared__ float Bs[8][128];
    const int tid  = threadIdx.x;
    const int brow = blockIdx.y, bcol = blockIdx.x;
    const int tr = tid >> 4, tc = tid & 15;
    const int aRow = tid >> 1, aCol = (tid & 1) * 4;
    const int bRow = tid >> 5, bCol = (tid & 31) * 4;
    const float* Ap = A + (size_t)(brow * 128) * K;
    const float* Bp = Bm + bcol * 128;

    float acc[8][8];
#pragma unroll
    for (int i = 0; i < 8; i++)
#pragma unroll
        for (int j = 0; j < 8; j++) acc[i][j] = 0.f;

    for (int k0 = 0; k0 < K; k0 += 8) {
        float4 av = *(const float4*)(Ap + (size_t)aRow * K + k0 + aCol);
        As[aCol + 0][aRow] = av.x; As[aCol + 1][aRow] = av.y;
        As[aCol + 2][aRow] = av.z; As[aCol + 3][aRow] = av.w;
        float4 bv = *(const float4*)(Bp + (size_t)(k0 + bRow) * N + bCol);
        *(float4*)&Bs[bRow][bCol] = bv;
        __syncthreads();
#pragma unroll
        for (int kk = 0; kk < 8; kk++) {
            float4 a0 = *(const float4*)&As[kk][tr * 8];
            float4 a1 = *(const float4*)&As[kk][tr * 8 + 4];
            float4 b0 = *(const float4*)&Bs[kk][tc * 8];
            float4 b1 = *(const float4*)&Bs[kk][tc * 8 + 4];
            float ar[8] = {a0.x,a0.y,a0.z,a0.w,a1.x,a1.y,a1.z,a1.w};
            float br[8] = {b0.x,b0.y,b0.z,b0.w,b1.x,b1.y,b1.z,b1.w};
#pragma unroll
            for (int i = 0; i < 8; i++)
#pragma unroll
                for (int j = 0; j < 8; j++)
                    acc[i][j] = fmaf(ar[i], br[j], acc[i][j]);
        }
        __syncthreads();
    }
#pragma unroll
    for (int i = 0; i < 8; i++) {
        int row = brow * 128 + tr * 8 + i;
#pragma unroll
        for (int j = 0; j < 8; j += 2) {
            int col = bcol * 128 + tc * 8 + j;
            float v0 = fmaxf(acc[i][j]     + bias[col],     0.f);
            float v1 = fmaxf(acc[i][j + 1] + bias[col + 1], 0.f);
            pack_a(g_h1pk, row, col, v0, v1);
        }
    }
}

// ---------------- pack weights into split B-fragment layout ----------------
__global__ void pack_weights(const float* __restrict__ W1, const float* __restrict__ Wr,
                             const float* __restrict__ Wk, const float* __restrict__ We2,
                             const float* __restrict__ W2)
{
    const int TOT1 = (N1 / 8) * 64 * 32;
    const int TOT2 = (N2 / 8) * 64 * 32;
    const int TOT3 = (UU / 8) * 64 * 32;
    int c = blockIdx.x * blockDim.x + threadIdx.x;
    float w[4];
    __nv_bfloat16* o;
    if (c < TOT1) {
        int cl = c;
        int nt8 = cl / 2048, rem = cl % 2048, kt = rem >> 5, l = rem & 31;
        int n  = nt8 * 8 + (l >> 2);
        int k0 = kt * 16 + (l & 3) * 2;
        const float* W; int ld, nn;
        if (n < 1024) { W = W1; ld = 1024; nn = n; }
        else          { W = Wr; ld = 4096; nn = n - 1024; }
        w[0] = W[(size_t)(k0    ) * ld + nn];
        w[1] = W[(size_t)(k0 + 1) * ld + nn];
        w[2] = W[(size_t)(k0 + 8) * ld + nn];
        w[3] = W[(size_t)(k0 + 9) * ld + nn];
        o = g_Wpk1 + (size_t)cl * 8;
    } else if (c < TOT1 + TOT2) {
        int cl = c - TOT1;
        int nt8 = cl / 2048, rem = cl % 2048, kt = rem >> 5, l = rem & 31;
        int n  = nt8 * 8 + (l >> 2);
        int k0 = kt * 16 + (l & 3) * 2;
        w[0] = Wk[(size_t)(k0    ) * 4096 + n];
        w[1] = Wk[(size_t)(k0 + 1) * 4096 + n];
        w[2] = Wk[(size_t)(k0 + 8) * 4096 + n];
        w[3] = Wk[(size_t)(k0 + 9) * 4096 + n];
        o = g_Wpk2 + (size_t)cl * 8;
    } else if (c < TOT1 + TOT2 + 2 * TOT3) {
        int cl = c - TOT1 - TOT2;
        const float* W = We2;
        __nv_bfloat16* dst = g_We2pk;
        if (cl >= TOT3) { cl -= TOT3; W = W2; dst = g_W2pk; }
        int nt8 = cl / 2048, rem = cl % 2048, kt = rem >> 5, l = rem & 31;
        int n  = nt8 * 8 + (l >> 2);
        int k0 = kt * 16 + (l & 3) * 2;
        w[0] = W[(size_t)(k0    ) * 1024 + n];
        w[1] = W[(size_t)(k0 + 1) * 1024 + n];
        w[2] = W[(size_t)(k0 + 8) * 1024 + n];
        w[3] = W[(size_t)(k0 + 9) * 1024 + n];
        o = dst + (size_t)cl * 8;
    } else return;
#pragma unroll
    for (int i = 0; i < 4; i++) split_bf16(w[i], o[i], o[4 + i]);
}

// ---------------- big split-bf16 HMMA (precompute) ----------------
__global__ __launch_bounds__(256)
void hgemm_big(const __nv_bfloat16* __restrict__ Apk,
               const __nv_bfloat16* __restrict__ Wpk,
               const float* __restrict__ bias, int doRelu, int N,
               __nv_bfloat16* __restrict__ outPk, __half* __restrict__ outH)
{
    const int tiles_n = N / 32;
    const int tm = blockIdx.x / tiles_n, tn = blockIdx.x % tiles_n;
    const int tid = threadIdx.x;
    const int w = tid >> 5, l = tid & 31;
    const int mt = w >> 1, np = w & 1;
    const int mtg = tm * 4 + mt;
    const uint4* a_it  = (const uint4*)Apk + ((size_t)mtg * 2048 + l) * 2;
    const int nt0 = tn * 4 + np * 2;
    const uint4* b0_it = (const uint4*)Wpk + (size_t)nt0 * 2048 + l;
    const uint4* b1_it = b0_it + 2048;

    float d0[4] = {0.f,0.f,0.f,0.f};
    float d1[4] = {0.f,0.f,0.f,0.f};
#pragma unroll 4
    for (int kt = 0; kt < 64; kt++) {
        uint4 aH = a_it[(size_t)kt * 64];
        uint4 aL = a_it[(size_t)kt * 64 + 1];
        uint4 b0 = b0_it[kt * 32];
        uint4 b1 = b1_it[kt * 32];
        uint2 b0H = make_uint2(b0.x, b0.y), b0L = make_uint2(b0.z, b0.w);
        uint2 b1H = make_uint2(b1.x, b1.y), b1L = make_uint2(b1.z, b1.w);
        mma16816(d0, aH, b0H);
        mma16816(d0, aH, b0L);
        mma16816(d0, aL, b0H);
        mma16816(d1, aH, b1H);
        mma16816(d1, aH, b1L);
        mma16816(d1, aL, b1H);
    }
    const int r0 = tm * 64 + mt * 16 + (l >> 2);
    const int c0 = tn * 32 + np * 16 + ((l & 3) << 1);
    float2 bbA = *(const float2*)&bias[c0];
    float2 bbB = *(const float2*)&bias[c0 + 8];
    d0[0] += bbA.x; d0[1] += bbA.y; d0[2] += bbA.x; d0[3] += bbA.y;
    d1[0] += bbB.x; d1[1] += bbB.y; d1[2] += bbB.x; d1[3] += bbB.y;
    if (doRelu) {
#pragma unroll
        for (int i = 0; i < 4; i++) {
            d0[i] = fmaxf(d0[i], 0.f);
            d1[i] = fmaxf(d1[i], 0.f);
        }
    }
    if (outH) {
        *(__half2*)&outH[(size_t)r0 * N + c0]           = __floats2half2_rn(d0[0], d0[1]);
        *(__half2*)&outH[(size_t)(r0 + 8) * N + c0]     = __floats2half2_rn(d0[2], d0[3]);
        *(__half2*)&outH[(size_t)r0 * N + c0 + 8]       = __floats2half2_rn(d1[0], d1[1]);
        *(__half2*)&outH[(size_t)(r0 + 8) * N + c0 + 8] = __floats2half2_rn(d1[2], d1[3]);
    }
    if (outPk) {
        pack_a(outPk, r0,     c0,     d0[0], d0[1]);
        pack_a(outPk, r0 + 8, c0,     d0[2], d0[3]);
        pack_a(outPk, r0,     c0 + 8, d1[0], d1[1]);
        pack_a(outPk, r0 + 8, c0 + 8, d1[2], d1[3]);
    }
}

// ---------------- init ----------------
__global__ void init_state(float* __restrict__ out)
{
    int idx = blockIdx.x * blockDim.x + threadIdx.x;
    if (idx < BB * UU) {
        g_c[idx] = 0.f;
        g_hpk[idx] = __float2bfloat16(0.f);
        g_hpk[BB * UU + idx] = __float2bfloat16(0.f);
    }
    if (idx < SEQ * BB) out[idx] = 0.f;
    if (idx < 16 * 32) g_grp[idx] = 0;
    if (idx == 0) g_root = 0;
}

// ---------------- smem-staged 64xN step-GEMM task (split-K half) ----------
template<int NJ>   // NJ = nt8 per warp (tile N = 16*NJ); NJ=5 -> 80 cols, NJ=4 -> 64
__device__ __forceinline__ void gtile(const uint4* __restrict__ Apk,
                                      const uint4* __restrict__ Wpk,
                                      float* __restrict__ C, int ldc,
                                      int n0, int khalf,
                                      uint4* sA, uint4* sB)
{
    constexpr int NT = 2 * NJ;
    const int tid = threadIdx.x;
    const int w = tid >> 5, l = tid & 31;
    const int mt = w >> 1, np = w & 1;
    const int nt8base = n0 >> 3;
    const int ktbase = khalf * 32;

    float d[NJ][4];
#pragma unroll
    for (int j = 0; j < NJ; j++)
#pragma unroll
        for (int i = 0; i < 4; i++) d[j][i] = 0.f;

    auto load = [&](int buf, int cix) {
        const int kt0 = ktbase + cix * 8;
#pragma unroll
        for (int i = tid; i < 1024; i += 256) {
            int lane = i & 31, mtt = (i >> 5) & 3, ktl = i >> 7;
            const uint4* src = Apk + ((size_t)(mtt * 64 + kt0 + ktl) * 32 + lane) * 2;
            cp16(&sA[(((buf * 2 + 0) * 8 + ktl) * 4 + mtt) * 32 + lane], src);
            cp16(&sA[(((buf * 2 + 1) * 8 + ktl) * 4 + mtt) * 32 + lane], src + 1);
        }
        for (int i = tid; i < NT * 8 * 32; i += 256) {
            int lane = i & 31, nt = (i >> 5) % NT, ktl = (i >> 5) / NT;
            const uint4* src = Wpk + (size_t)((nt8base + nt) * 64 + kt0 + ktl) * 32 + lane;
            cp16(&sB[((buf * 8 + ktl) * NT + nt) * 32 + lane], src);
        }
        cp_commit();
    };

    load(0, 0);
    for (int c = 0; c < 4; c++) {
        if (c < 3) { load((c + 1) & 1, c + 1); cp_wait<1>(); }
        else       { cp_wait<0>(); }
        __syncthreads();
        const int buf = c & 1;
#pragma unroll
        for (int ktl = 0; ktl < 8; ktl++) {
            uint4 aH = sA[(((buf * 2 + 0) * 8 + ktl) * 4 + mt) * 32 + l];
            uint4 aL = sA[(((buf * 2 + 1) * 8 + ktl) * 4 + mt) * 32 + l];
#pragma unroll
            for (int j = 0; j < NJ; j++) {
                uint4 b = sB[((buf * 8 + ktl) * NT + np * NJ + j) * 32 + l];
                uint2 bH = make_uint2(b.x, b.y), bL = make_uint2(b.z, b.w);
                mma16816(d[j], aH, bH);
                mma16816(d[j], aH, bL);
                mma16816(d[j], aL, bH);
            }
        }
        __syncthreads();
    }
    const int r0 = mt * 16 + (l >> 2);
#pragma unroll
    for (int j = 0; j < NJ; j++) {
        const int c0 = n0 + (np * NJ + j) * 8 + ((l & 3) << 1);
        *(float2*)&C[(size_t)r0 * ldc + c0]       = make_float2(d[j][0], d[j][1]);
        *(float2*)&C[(size_t)(r0 + 8) * ldc + c0] = make_float2(d[j][2], d[j][3]);
    }
}

// ---------------- persistent decode (uniform phases, 5 bars/step) ----------
extern __shared__ uint4 dynsm[];
__global__ __launch_bounds__(256, 1)
void decode_persistent(const float* __restrict__ b1, const float* __restrict__ V,
                       const float* __restrict__ bl, const float* __restrict__ Wo,
                       const float* __restrict__ bo, float* __restrict__ out)
{
    __shared__ float sm[256];
    __shared__ float red[8];
    uint4* sA = dynsm;          // 4096 uint4 = 64 KB
    uint4* sB = dynsm + 4096;   // up to 5120 uint4 = 80 KB
    const int tid  = threadIdx.x;
    const int bid  = blockIdx.x;
    const int warp = tid >> 5, lane = tid & 31;

    const uint4* hpk_u4  = (const uint4*)g_hpk;
    const uint4* cpk_u4  = (const uint4*)g_cpk;
    const uint4* wpk1_u4 = (const uint4*)g_Wpk1;
    const uint4* wpk2_u4 = (const uint4*)g_Wpk2;

    for (int s = 0; s < SEQ; s++) {
        // ---- phase 1: qp[kh] = h @ [W1|Wr] (64 tiles x 80 cols, split-K2) ----
        {
            const int tile = bid & 63, kh = bid >> 6;
            gtile<5>(hpk_u4, wpk1_u4, &g_qp[kh][0][0], N1, tile * 80, kh, sA, sB);
        }
        grid_bar();

        // ---- phase 2: scores for (b, thalf) ----
        {
            const int b = bid >> 1, thalf = bid & 1;
            float qr[32], vr[32];
#pragma unroll
            for (int it = 0; it < 4; it++) {
                const int base = it * 256 + lane * 8;
#pragma unroll
                for (int k2 = 0; k2 < 8; k2 += 4) {
                    float4 q0 = *(const float4*)&g_qp[0][b][base + k2];
                    float4 q1 = *(const float4*)&g_qp[1][b][base + k2];
                    float4 bb = *(const float4*)&b1[base + k2];
                    float4 vv = *(const float4*)&V[base + k2];
                    qr[it*8+k2+0] = q0.x + q1.x + bb.x;  vr[it*8+k2+0] = vv.x;
                    qr[it*8+k2+1] = q0.y + q1.y + bb.y;  vr[it*8+k2+1] = vv.y;
                    qr[it*8+k2+2] = q0.z + q1.z + bb.z;  vr[it*8+k2+2] = vv.z;
                    qr[it*8+k2+3] = q0.w + q1.w + bb.w;  vr[it*8+k2+3] = vv.w;
                }
            }
            for (int t = warp; t < 128; t += 8) {
                const int tt = thalf * 128 + t;
                const uint4* kp = (const uint4*)(g_keh + ((size_t)(b * 256 + tt)) * 1024);
                float s0 = 0.f;
#pragma unroll
                for (int it = 0; it < 4; it++) {
                    uint4 kv = kp[it * 32 + lane];
                    float2 f0 = __half22float2(*(__half2*)&kv.x);
                    float2 f1 = __half22float2(*(__half2*)&kv.y);
                    float2 f2 = __half22float2(*(__half2*)&kv.z);
                    float2 f3 = __half22float2(*(__half2*)&kv.w);
                    s0 += vr[it*8+0] * tanh_hw(qr[it*8+0] + f0.x);
                    s0 += vr[it*8+1] * tanh_hw(qr[it*8+1] + f0.y);
                    s0 += vr[it*8+2] * tanh_hw(qr[it*8+2] + f1.x);
                    s0 += vr[it*8+3] * tanh_hw(qr[it*8+3] + f1.y);
                    s0 += vr[it*8+4] * tanh_hw(qr[it*8+4] + f2.x);
                    s0 += vr[it*8+5] * tanh_hw(qr[it*8+5] + f2.y);
                    s0 += vr[it*8+6] * tanh_hw(qr[it*8+6] + f3.x);
                    s0 += vr[it*8+7] * tanh_hw(qr[it*8+7] + f3.y);
                }
#pragma unroll
                for (int o = 16; o; o >>= 1) s0 += __shfl_xor_sync(0xffffffffu, s0, o);
                if (!lane) g_sc[b * 256 + tt] = s0;
            }
        }
        grid_bar();

        // ---- phase 3: softmax (redundant) + ctx for (b, uhalf) ----
        {
            const int b = bid >> 1, uhalf = bid & 1;
            float v = g_sc[b * 256 + tid];
            float m = v;
#pragma unroll
            for (int o = 16; o; o >>= 1) m = fmaxf(m, __shfl_xor_sync(0xffffffffu, m, o));
            if (!lane) red[warp] = m;
            __syncthreads();
            float bm = red[0];
#pragma unroll
            for (int w2 = 1; w2 < 8; w2++) bm = fmaxf(bm, red[w2]);
            __syncthreads();
            float e = __expf(v - bm);
            float ss = e;
#pragma unroll
            for (int o = 16; o; o >>= 1) ss += __shfl_xor_sync(0xffffffffu, ss, o);
            if (!lane) red[warp] = ss;
            __syncthreads();
            float bs = 0.f;
#pragma unroll
            for (int w2 = 0; w2 < 8; w2++) bs += red[w2];
            sm[tid] = __fdividef(e, bs);
            __syncthreads();

            const int u0 = uhalf * 512 + tid * 2;
            const __half2* xb = (const __half2*)(g_xh + (size_t)b * 256 * 1024 + u0);
            float ax = 0.f, ay = 0.f;
#pragma unroll 8
            for (int t = 0; t < 256; t++) {
                float2 xv = __half22float2(xb[(size_t)t * 512]);
                float wt = sm[t];
                ax = fmaf(wt, xv.x, ax);
                ay = fmaf(wt, xv.y, ay);
            }
            pack_a(g_cpk, b, u0, ax, ay);
            __syncthreads();
        }
        grid_bar();

        // ---- phase 4: zp[kh] = ctx @ Wk (64 tiles x 64 cols, split-K2) ----
        {
            const int tile = bid & 63, kh = bid >> 6;
            gtile<4>(cpk_u4, wpk2_u4, &g_zp[kh][0][0], N2, tile * 64, kh, sA, sB);
        }
        grid_bar();

        // ---- phase 5: LSTM gates + state + projection for (b2, jhalf) ----
        {
            const int b2 = bid >> 1, jhalf = bid & 1;
            const int j0 = jhalf * 512 + tid * 2;
            const float* z0 = g_zp[0][b2]; const float* z1 = g_zp[1][b2];
            const float* h0 = g_qp[0][b2] + 1024; const float* h1 = g_qp[1][b2] + 1024;
            float2 a0, a1, c0, c1;
            a0 = *(const float2*)&z0[j0];        a1 = *(const float2*)&z1[j0];
            c0 = *(const float2*)&h0[j0];        c1 = *(const float2*)&h1[j0];
            float2 zi = { bl[j0]   + a0.x + a1.x + c0.x + c1.x,
                          bl[j0+1] + a0.y + a1.y + c0.y + c1.y };
            a0 = *(const float2*)&z0[1024+j0];   a1 = *(const float2*)&z1[1024+j0];
            c0 = *(const float2*)&h0[1024+j0];   c1 = *(const float2*)&h1[1024+j0];
            float2 zf = { bl[1024+j0]   + a0.x + a1.x + c0.x + c1.x,
                          bl[1024+j0+1] + a0.y + a1.y + c0.y + c1.y };
            a0 = *(const float2*)&z0[2048+j0];   a1 = *(const float2*)&z1[2048+j0];
            c0 = *(const float2*)&h0[2048+j0];   c1 = *(const float2*)&h1[2048+j0];
            float2 zg = { bl[2048+j0]   + a0.x + a1.x + c0.x + c1.x,
                          bl[2048+j0+1] + a0.y + a1.y + c0.y + c1.y };
            a0 = *(const float2*)&z0[3072+j0];   a1 = *(const float2*)&z1[3072+j0];
            c0 = *(const float2*)&h0[3072+j0];   c1 = *(const float2*)&h1[3072+j0];
            float2 zo = { bl[3072+j0]   + a0.x + a1.x + c0.x + c1.x,
                          bl[3072+j0+1] + a0.y + a1.y + c0.y + c1.y };

            float2 cold = *(const float2*)&g_c[b2 * 1024 + j0];
            float cx = sigf(zf.x) * cold.x + sigf(zi.x) * fast_tanh(zg.x);
            float cy = sigf(zf.y) * cold.y + sigf(zi.y) * fast_tanh(zg.y);
            float hx = sigf(zo.x) * fast_tanh(cx);
            float hy = sigf(zo.y) * fast_tanh(cy);
            *(float2*)&g_c[b2 * 1024 + j0] = make_float2(cx, cy);
            pack_a(g_hpk, b2, j0, hx, hy);

            float p = hx * Wo[j0] + hy * Wo[j0 + 1];
            if (tid == 0 && jhalf == 0) p += bo[0];
#pragma unroll
            for (int o = 16; o; o >>= 1) p += __shfl_xor_sync(0xffffffffu, p, o);
            if (!lane) red[warp] = p;
            __syncthreads();
            if (tid == 0) {
                float acc = 0.f;
#pragma unroll
                for (int w2 = 0; w2 < 8; w2++) acc += red[w2];
                atomicAdd(&out[s * 64 + b2], acc);
            }
            __syncthreads();
        }
        grid_bar();
    }
}

// ---------------- host launcher ----------------
extern "C" void kernel_launch(void* const* d_in, const int* in_sizes, int n_in,
                              void* d_out, int out_size)
{
    const float* inputs = (const float*)d_in[0];
    const float* We1 = (const float*)d_in[1];  const float* be1 = (const float*)d_in[2];
    const float* We2 = (const float*)d_in[3];  const float* be2 = (const float*)d_in[4];
    const float* W1  = (const float*)d_in[5];  const float* b1  = (const float*)d_in[6];
    const float* W2  = (const float*)d_in[7];  const float* b2k = (const float*)d_in[8];
    const float* V   = (const float*)d_in[9];  /* bV shift-invariant in softmax */
    const float* Wk  = (const float*)d_in[11]; const float* Wr  = (const float*)d_in[12];
    const float* bl  = (const float*)d_in[13]; const float* Wo  = (const float*)d_in[14];
    const float* bo  = (const float*)d_in[15];
    float* out = (float*)d_out;

    void *p_h1pk, *p_xpk, *p_xh, *p_keh, *p_We2pk, *p_W2pk;
    cudaGetSymbolAddress(&p_h1pk,  g_h1pk);
    cudaGetSymbolAddress(&p_xpk,   g_xpk);
    cudaGetSymbolAddress(&p_xh,    g_xh);
    cudaGetSymbolAddress(&p_keh,   g_keh);
    cudaGetSymbolAddress(&p_We2pk, g_We2pk);
    cudaGetSymbolAddress(&p_W2pk,  g_W2pk);

    const int DYN_SMEM = (4096 + 5120) * 16;   // 144 KB: sA 64K + sB 80K
    static int attr_set = 0;
    if (!attr_set) {
        cudaFuncSetAttribute(decode_persistent,
                             cudaFuncAttributeMaxDynamicSharedMemorySize, DYN_SMEM);
        attr_set = 1;
    }

    pack_weights<<<5632, 512>>>(W1, Wr, Wk, We2, W2);
    sgemm128_pack<<<dim3(UU / 128, NROW / 128), 256>>>(inputs, We1, be1, UU, DINN);
    hgemm_big<<<(NROW / 64) * (UU / 32), 256>>>(
        (const __nv_bfloat16*)p_h1pk, (const __nv_bfloat16*)p_We2pk, be2, 1, UU,
        (__nv_bfloat16*)p_xpk, (__half*)p_xh);
    hgemm_big<<<(NROW / 64) * (UU / 32), 256>>>(
        (const __nv_bfloat16*)p_xpk, (const __nv_bfloat16*)p_W2pk, b2k, 0, UU,
        (__nv_bfloat16*)0, (__half*)p_keh);
    init_state<<<64, 1024>>>(out);
    decode_persistent<<<NB, 256, DYN_SMEM>>>(b1, V, bl, Wo, bo, out);
}

// round 14
// speedup vs baseline: 1.1497x; 1.0293x over previous
#include <cuda_runtime.h>
#include <cuda_bf16.h>
#include <cuda_fp16.h>
#include <math.h>

#define BB   64
#define TT   256
#define DINN 128
#define UU   1024
#define SEQ  256
#define NROW (BB*TT)
#define NB   128
#define N1   5120       // [W1 | Wr]
#define N2   4096       // Wk

// ---------------- device scratch ----------------
__device__ __nv_bfloat16 g_h1pk[(size_t)NROW * UU * 2];   // h1 A-frags (KT=64)
__device__ __nv_bfloat16 g_xpk [(size_t)NROW * UU * 2];   // x  A-frags (KT=64)
__device__ __half g_xh [(size_t)NROW * UU];               // x  fp16 linear
__device__ __half g_keh[(size_t)NROW * UU];               // keys fp16 linear
__device__ __nv_bfloat16 g_Wpk1 [(size_t)UU * N1 * 2];    // B-frags [W1|Wr]
__device__ __nv_bfloat16 g_Wpk2 [(size_t)UU * N2 * 2];    // B-frags Wk
__device__ __nv_bfloat16 g_We2pk[(size_t)UU * UU * 2];
__device__ __nv_bfloat16 g_W2pk [(size_t)UU * UU * 2];
__device__ __nv_bfloat16 g_hpk[BB * UU * 2];              // A-frags h
__device__ __nv_bfloat16 g_cpk[BB * UU * 2];              // A-frags ctx
__device__ float g_qp[2][BB][N1];                         // split-K partials
__device__ float g_zp[2][BB][N2];
__device__ float g_c [BB * UU];
__device__ float g_sc[BB * TT];
// hierarchical barrier state (group counters padded to 128B lines)
__device__ unsigned g_grp[16 * 32];
__device__ unsigned g_root    = 0;
__device__ unsigned g_bar_gen = 0;

// ---------------- helpers ----------------
__device__ __forceinline__ float tanh_hw(float x) {
    float y; asm("tanh.approx.f32 %0, %1;" : "=f"(y) : "f"(x)); return y;
}
__device__ __forceinline__ float fast_tanh(float x) {
    float e = __expf(2.0f * x);
    return 1.0f - __fdividef(2.0f, e + 1.0f);
}
__device__ __forceinline__ float sigf(float x) {
    return __fdividef(1.0f, 1.0f + __expf(-x));
}
__device__ __forceinline__ void mma16816(float d[4], const uint4& a, const uint2& b) {
    asm("mma.sync.aligned.m16n8k16.row.col.f32.bf16.bf16.f32 "
        "{%0,%1,%2,%3},{%4,%5,%6,%7},{%8,%9},{%0,%1,%2,%3};"
        : "+f"(d[0]), "+f"(d[1]), "+f"(d[2]), "+f"(d[3])
        : "r"(a.x), "r"(a.y), "r"(a.z), "r"(a.w), "r"(b.x), "r"(b.y));
}
__device__ __forceinline__ void cp16(void* smem, const void* g) {
    unsigned s = (unsigned)__cvta_generic_to_shared(smem);
    asm volatile("cp.async.cg.shared.global [%0], [%1], 16;" :: "r"(s), "l"(g));
}
__device__ __forceinline__ void cp_commit() {
    asm volatile("cp.async.commit_group;");
}
template<int N> __device__ __forceinline__ void cp_wait() {
    asm volatile("cp.async.wait_group %0;" :: "n"(N));
}

// two-level grid barrier: 16 groups x 8 arrivals -> root of 16; busy spin
__device__ __forceinline__ void grid_bar() {
    __syncthreads();
    if (threadIdx.x == 0) {
        unsigned gen;
        asm volatile("ld.acquire.gpu.u32 %0, [%1];" : "=r"(gen) : "l"(&g_bar_gen));
        unsigned* gc = &g_grp[(blockIdx.x >> 3) * 32];
        unsigned prev;
        asm volatile("atom.acq_rel.gpu.add.u32 %0, [%1], 1;" : "=r"(prev) : "l"(gc));
        bool released = false;
        if (prev == 7) {   // last of group -> arrive at root
            unsigned p2;
            asm volatile("atom.acq_rel.gpu.add.u32 %0, [%1], 1;"
                         : "=r"(p2) : "l"(&g_root));
            if (p2 == 15) { // last overall -> reset counters, release
#pragma unroll
                for (int g = 0; g < 16; g++)
                    asm volatile("st.relaxed.gpu.u32 [%0], 0;" :: "l"(&g_grp[g * 32]));
                asm volatile("st.relaxed.gpu.u32 [%0], 0;" :: "l"(&g_root));
                unsigned d;
                asm volatile("atom.add.release.gpu.u32 %0, [%1], 1;"
                             : "=r"(d) : "l"(&g_bar_gen));
                released = true;
            }
        }
        if (!released) {
            unsigned g;
            do {
                asm volatile("ld.acquire.gpu.u32 %0, [%1];" : "=r"(g) : "l"(&g_bar_gen));
            } while (g == gen);
        }
    }
    __syncthreads();
}

// ---------------- split + A-fragment pack ----------------
__device__ __forceinline__ void split_bf16(float v, __nv_bfloat16& hi, __nv_bfloat16& lo) {
    hi = __float2bfloat16(v);
    lo = __float2bfloat16(v - __bfloat162float(hi));
}
__device__ __forceinline__ void pack_a(__nv_bfloat16* dst, int row, int u,
                                       float vx, float vy)
{
    const int mt = row >> 4, rm = row & 15;
    const int kt = u >> 4,  cm = u & 15;          // u even
    const int lane = (rm & 7) * 4 + ((cm & 7) >> 1);
    const int reg  = (rm >> 3) + ((cm >> 3) & 1) * 2;
    const size_t base = ((size_t)(mt * 64 + kt) * 32 + lane) * 16;
    __nv_bfloat16 hx, lx, hy, ly;
    split_bf16(vx, hx, lx);
    split_bf16(vy, hy, ly);
    __nv_bfloat162 hp; hp.x = hx; hp.y = hy;
    __nv_bfloat162 lp; lp.x = lx; lp.y = ly;
    *(__nv_bfloat162*)&dst[base + reg * 2]     = hp;
    *(__nv_bfloat162*)&dst[base + 8 + reg * 2] = lp;
}

// ---------------- GEMM1 (fp32 SIMT, K=128): h1pk = pack(relu(inputs@We1+be1)) ----
__global__ __launch_bounds__(256, 2)
void sgemm128_pack(const float* __restrict__ A, const float* __restrict__ Bm,
                   const float* __restrict__ bias, int N, int K)
{
    __shared__ float As[8][128];
    __shared__ float Bs[8][128];
    const int tid  = threadIdx.x;
    const int brow = blockIdx.y, bcol = blockIdx.x;
    const int tr = tid >> 4, tc = tid & 15;
    const int aRow = tid >> 1, aCol = (tid & 1) * 4;
    const int bRow = tid >> 5, bCol = (tid & 31) * 4;
    const float* Ap = A + (size_t)(brow * 128) * K;
    const float* Bp = Bm + bcol * 128;

    float acc[8][8];
#pragma unroll
    for (int i = 0; i < 8; i++)
#pragma unroll
        for (int j = 0; j < 8; j++) acc[i][j] = 0.f;

    for (int k0 = 0; k0 < K; k0 += 8) {
        float4 av = *(const float4*)(Ap + (size_t)aRow * K + k0 + aCol);
        As[aCol + 0][aRow] = av.x; As[aCol + 1][aRow] = av.y;
        As[aCol + 2][aRow] = av.z; As[aCol + 3][aRow] = av.w;
        float4 bv = *(const float4*)(Bp + (size_t)(k0 + bRow) * N + bCol);
        *(float4*)&Bs[bRow][bCol] = bv;
        __syncthreads();
#pragma unroll
        for (int kk = 0; kk < 8; kk++) {
            float4 a0 = *(const float4*)&As[kk][tr * 8];
            float4 a1 = *(const float4*)&As[kk][tr * 8 + 4];
            float4 b0 = *(const float4*)&Bs[kk][tc * 8];
            float4 b1 = *(const float4*)&Bs[kk][tc * 8 + 4];
            float ar[8] = {a0.x,a0.y,a0.z,a0.w,a1.x,a1.y,a1.z,a1.w};
            float br[8] = {b0.x,b0.y,b0.z,b0.w,b1.x,b1.y,b1.z,b1.w};
#pragma unroll
            for (int i = 0; i < 8; i++)
#pragma unroll
                for (int j = 0; j < 8; j++)
                    acc[i][j] = fmaf(ar[i], br[j], acc[i][j]);
        }
        __syncthreads();
    }
#pragma unroll
    for (int i = 0; i < 8; i++) {
        int row = brow * 128 + tr * 8 + i;
#pragma unroll
        for (int j = 0; j < 8; j += 2) {
            int col = bcol * 128 + tc * 8 + j;
            float v0 = fmaxf(acc[i][j]     + bias[col],     0.f);
            float v1 = fmaxf(acc[i][j + 1] + bias[col + 1], 0.f);
            pack_a(g_h1pk, row, col, v0, v1);
        }
    }
}

// ---------------- pack weights into split B-fragment layout ----------------
__global__ void pack_weights(const float* __restrict__ W1, const float* __restrict__ Wr,
                             const float* __restrict__ Wk, const float* __restrict__ We2,
                             const float* __restrict__ W2)
{
    const int TOT1 = (N1 / 8) * 64 * 32;
    const int TOT2 = (N2 / 8) * 64 * 32;
    const int TOT3 = (UU / 8) * 64 * 32;
    int c = blockIdx.x * blockDim.x + threadIdx.x;
    float w[4];
    __nv_bfloat16* o;
    if (c < TOT1) {
        int cl = c;
        int nt8 = cl / 2048, rem = cl % 2048, kt = rem >> 5, l = rem & 31;
        int n  = nt8 * 8 + (l >> 2);
        int k0 = kt * 16 + (l & 3) * 2;
        const float* W; int ld, nn;
        if (n < 1024) { W = W1; ld = 1024; nn = n; }
        else          { W = Wr; ld = 4096; nn = n - 1024; }
        w[0] = W[(size_t)(k0    ) * ld + nn];
        w[1] = W[(size_t)(k0 + 1) * ld + nn];
        w[2] = W[(size_t)(k0 + 8) * ld + nn];
        w[3] = W[(size_t)(k0 + 9) * ld + nn];
        o = g_Wpk1 + (size_t)cl * 8;
    } else if (c < TOT1 + TOT2) {
        int cl = c - TOT1;
        int nt8 = cl / 2048, rem = cl % 2048, kt = rem >> 5, l = rem & 31;
        int n  = nt8 * 8 + (l >> 2);
        int k0 = kt * 16 + (l & 3) * 2;
        w[0] = Wk[(size_t)(k0    ) * 4096 + n];
        w[1] = Wk[(size_t)(k0 + 1) * 4096 + n];
        w[2] = Wk[(size_t)(k0 + 8) * 4096 + n];
        w[3] = Wk[(size_t)(k0 + 9) * 4096 + n];
        o = g_Wpk2 + (size_t)cl * 8;
    } else if (c < TOT1 + TOT2 + 2 * TOT3) {
        int cl = c - TOT1 - TOT2;
        const float* W = We2;
        __nv_bfloat16* dst = g_We2pk;
        if (cl >= TOT3) { cl -= TOT3; W = W2; dst = g_W2pk; }
        int nt8 = cl / 2048, rem = cl % 2048, kt = rem >> 5, l = rem & 31;
        int n  = nt8 * 8 + (l >> 2);
        int k0 = kt * 16 + (l & 3) * 2;
        w[0] = W[(size_t)(k0    ) * 1024 + n];
        w[1] = W[(size_t)(k0 + 1) * 1024 + n];
        w[2] = W[(size_t)(k0 + 8) * 1024 + n];
        w[3] = W[(size_t)(k0 + 9) * 1024 + n];
        o = dst + (size_t)cl * 8;
    } else return;
#pragma unroll
    for (int i = 0; i < 4; i++) split_bf16(w[i], o[i], o[4 + i]);
}

// ---------------- big split-bf16 HMMA (precompute) ----------------
__global__ __launch_bounds__(256)
void hgemm_big(const __nv_bfloat16* __restrict__ Apk,
               const __nv_bfloat16* __restrict__ Wpk,
               const float* __restrict__ bias, int doRelu, int N,
               __nv_bfloat16* __restrict__ outPk, __half* __restrict__ outH)
{
    const int tiles_n = N / 32;
    const int tm = blockIdx.x / tiles_n, tn = blockIdx.x % tiles_n;
    const int tid = threadIdx.x;
    const int w = tid >> 5, l = tid & 31;
    const int mt = w >> 1, np = w & 1;
    const int mtg = tm * 4 + mt;
    const uint4* a_it  = (const uint4*)Apk + ((size_t)mtg * 2048 + l) * 2;
    const int nt0 = tn * 4 + np * 2;
    const uint4* b0_it = (const uint4*)Wpk + (size_t)nt0 * 2048 + l;
    const uint4* b1_it = b0_it + 2048;

    float d0[4] = {0.f,0.f,0.f,0.f};
    float d1[4] = {0.f,0.f,0.f,0.f};
#pragma unroll 4
    for (int kt = 0; kt < 64; kt++) {
        uint4 aH = a_it[(size_t)kt * 64];
        uint4 aL = a_it[(size_t)kt * 64 + 1];
        uint4 b0 = b0_it[kt * 32];
        uint4 b1 = b1_it[kt * 32];
        uint2 b0H = make_uint2(b0.x, b0.y), b0L = make_uint2(b0.z, b0.w);
        uint2 b1H = make_uint2(b1.x, b1.y), b1L = make_uint2(b1.z, b1.w);
        mma16816(d0, aH, b0H);
        mma16816(d0, aH, b0L);
        mma16816(d0, aL, b0H);
        mma16816(d1, aH, b1H);
        mma16816(d1, aH, b1L);
        mma16816(d1, aL, b1H);
    }
    const int r0 = tm * 64 + mt * 16 + (l >> 2);
    const int c0 = tn * 32 + np * 16 + ((l & 3) << 1);
    float2 bbA = *(const float2*)&bias[c0];
    float2 bbB = *(const float2*)&bias[c0 + 8];
    d0[0] += bbA.x; d0[1] += bbA.y; d0[2] += bbA.x; d0[3] += bbA.y;
    d1[0] += bbB.x; d1[1] += bbB.y; d1[2] += bbB.x; d1[3] += bbB.y;
    if (doRelu) {
#pragma unroll
        for (int i = 0; i < 4; i++) {
            d0[i] = fmaxf(d0[i], 0.f);
            d1[i] = fmaxf(d1[i], 0.f);
        }
    }
    if (outH) {
        *(__half2*)&outH[(size_t)r0 * N + c0]           = __floats2half2_rn(d0[0], d0[1]);
        *(__half2*)&outH[(size_t)(r0 + 8) * N + c0]     = __floats2half2_rn(d0[2], d0[3]);
        *(__half2*)&outH[(size_t)r0 * N + c0 + 8]       = __floats2half2_rn(d1[0], d1[1]);
        *(__half2*)&outH[(size_t)(r0 + 8) * N + c0 + 8] = __floats2half2_rn(d1[2], d1[3]);
    }
    if (outPk) {
        pack_a(outPk, r0,     c0,     d0[0], d0[1]);
        pack_a(outPk, r0 + 8, c0,     d0[2], d0[3]);
        pack_a(outPk, r0,     c0 + 8, d1[0], d1[1]);
        pack_a(outPk, r0 + 8, c0 + 8, d1[2], d1[3]);
    }
}

// ---------------- init ----------------
__global__ void init_state(float* __restrict__ out)
{
    int idx = blockIdx.x * blockDim.x + threadIdx.x;
    if (idx < BB * UU) {
        g_c[idx] = 0.f;
        g_hpk[idx] = __float2bfloat16(0.f);
        g_hpk[BB * UU + idx] = __float2bfloat16(0.f);
    }
    if (idx < SEQ * BB) out[idx] = 0.f;
    if (idx < 16 * 32) g_grp[idx] = 0;
    if (idx == 0) g_root = 0;
}

// ---------------- smem-staged 64xN step-GEMM task (split-K half) ----------
template<int NJ>   // NJ = nt8 per warp (tile N = 16*NJ); NJ=5 -> 80 cols, NJ=4 -> 64
__device__ __forceinline__ void gtile(const uint4* __restrict__ Apk,
                                      const uint4* __restrict__ Wpk,
                                      float* __restrict__ C, int ldc,
                                      int n0, int khalf,
                                      uint4* sA, uint4* sB)
{
    constexpr int NT = 2 * NJ;
    const int tid = threadIdx.x;
    const int w = tid >> 5, l = tid & 31;
    const int mt = w >> 1, np = w & 1;
    const int nt8base = n0 >> 3;
    const int ktbase = khalf * 32;

    float d[NJ][4];
#pragma unroll
    for (int j = 0; j < NJ; j++)
#pragma unroll
        for (int i = 0; i < 4; i++) d[j][i] = 0.f;

    auto load = [&](int buf, int cix) {
        const int kt0 = ktbase + cix * 8;
#pragma unroll
        for (int i = tid; i < 1024; i += 256) {
            int lane = i & 31, mtt = (i >> 5) & 3, ktl = i >> 7;
            const uint4* src = Apk + ((size_t)(mtt * 64 + kt0 + ktl) * 32 + lane) * 2;
            cp16(&sA[(((buf * 2 + 0) * 8 + ktl) * 4 + mtt) * 32 + lane], src);
            cp16(&sA[(((buf * 2 + 1) * 8 + ktl) * 4 + mtt) * 32 + lane], src + 1);
        }
        for (int i = tid; i < NT * 8 * 32; i += 256) {
            int lane = i & 31, nt = (i >> 5) % NT, ktl = (i >> 5) / NT;
            const uint4* src = Wpk + (size_t)((nt8base + nt) * 64 + kt0 + ktl) * 32 + lane;
            cp16(&sB[((buf * 8 + ktl) * NT + nt) * 32 + lane], src);
        }
        cp_commit();
    };

    load(0, 0);
    for (int c = 0; c < 4; c++) {
        if (c < 3) { load((c + 1) & 1, c + 1); cp_wait<1>(); }
        else       { cp_wait<0>(); }
        __syncthreads();
        const int buf = c & 1;
#pragma unroll
        for (int ktl = 0; ktl < 8; ktl++) {
            uint4 aH = sA[(((buf * 2 + 0) * 8 + ktl) * 4 + mt) * 32 + l];
            uint4 aL = sA[(((buf * 2 + 1) * 8 + ktl) * 4 + mt) * 32 + l];
#pragma unroll
            for (int j = 0; j < NJ; j++) {
                uint4 b = sB[((buf * 8 + ktl) * NT + np * NJ + j) * 32 + l];
                uint2 bH = make_uint2(b.x, b.y), bL = make_uint2(b.z, b.w);
                mma16816(d[j], aH, bH);
                mma16816(d[j], aH, bL);
                mma16816(d[j], aL, bH);
            }
        }
        __syncthreads();
    }
    const int r0 = mt * 16 + (l >> 2);
#pragma unroll
    for (int j = 0; j < NJ; j++) {
        const int c0 = n0 + (np * NJ + j) * 8 + ((l & 3) << 1);
        *(float2*)&C[(size_t)r0 * ldc + c0]       = make_float2(d[j][0], d[j][1]);
        *(float2*)&C[(size_t)(r0 + 8) * ldc + c0] = make_float2(d[j][2], d[j][3]);
    }
}

// ---------------- persistent decode (uniform phases, 5 bars/step) ----------
extern __shared__ uint4 dynsm[];
__global__ __launch_bounds__(256, 1)
void decode_persistent(const float* __restrict__ b1, const float* __restrict__ V,
                       const float* __restrict__ bl, const float* __restrict__ Wo,
                       const float* __restrict__ bo, float* __restrict__ out)
{
    __shared__ float sm[256];
    __shared__ float red[8];
    uint4* sA = dynsm;          // 4096 uint4 = 64 KB
    uint4* sB = dynsm + 4096;   // up to 5120 uint4 = 80 KB
    const int tid  = threadIdx.x;
    const int bid  = blockIdx.x;
    const int warp = tid >> 5, lane = tid & 31;

    const uint4* hpk_u4  = (const uint4*)g_hpk;
    const uint4* cpk_u4  = (const uint4*)g_cpk;
    const uint4* wpk1_u4 = (const uint4*)g_Wpk1;
    const uint4* wpk2_u4 = (const uint4*)g_Wpk2;

    for (int s = 0; s < SEQ; s++) {
        // ---- phase 1: qp[kh] = h @ [W1|Wr] (64 tiles x 80 cols, split-K2) ----
        {
            const int tile = bid & 63, kh = bid >> 6;
            gtile<5>(hpk_u4, wpk1_u4, &g_qp[kh][0][0], N1, tile * 80, kh, sA, sB);
        }
        grid_bar();

        // ---- phase 2: scores for (b, thalf) ----
        {
            const int b = bid >> 1, thalf = bid & 1;
            float qr[32], vr[32];
#pragma unroll
            for (int it = 0; it < 4; it++) {
                const int base = it * 256 + lane * 8;
#pragma unroll
                for (int k2 = 0; k2 < 8; k2 += 4) {
                    float4 q0 = *(const float4*)&g_qp[0][b][base + k2];
                    float4 q1 = *(const float4*)&g_qp[1][b][base + k2];
                    float4 bb = *(const float4*)&b1[base + k2];
                    float4 vv = *(const float4*)&V[base + k2];
                    qr[it*8+k2+0] = q0.x + q1.x + bb.x;  vr[it*8+k2+0] = vv.x;
                    qr[it*8+k2+1] = q0.y + q1.y + bb.y;  vr[it*8+k2+1] = vv.y;
                    qr[it*8+k2+2] = q0.z + q1.z + bb.z;  vr[it*8+k2+2] = vv.z;
                    qr[it*8+k2+3] = q0.w + q1.w + bb.w;  vr[it*8+k2+3] = vv.w;
                }
            }
            for (int t = warp; t < 128; t += 8) {
                const int tt = thalf * 128 + t;
                const uint4* kp = (const uint4*)(g_keh + ((size_t)(b * 256 + tt)) * 1024);
                float s0 = 0.f;
#pragma unroll
                for (int it = 0; it < 4; it++) {
                    uint4 kv = kp[it * 32 + lane];
                    float2 f0 = __half22float2(*(__half2*)&kv.x);
                    float2 f1 = __half22float2(*(__half2*)&kv.y);
                    float2 f2 = __half22float2(*(__half2*)&kv.z);
                    float2 f3 = __half22float2(*(__half2*)&kv.w);
                    s0 += vr[it*8+0] * tanh_hw(qr[it*8+0] + f0.x);
                    s0 += vr[it*8+1] * tanh_hw(qr[it*8+1] + f0.y);
                    s0 += vr[it*8+2] * tanh_hw(qr[it*8+2] + f1.x);
                    s0 += vr[it*8+3] * tanh_hw(qr[it*8+3] + f1.y);
                    s0 += vr[it*8+4] * tanh_hw(qr[it*8+4] + f2.x);
                    s0 += vr[it*8+5] * tanh_hw(qr[it*8+5] + f2.y);
                    s0 += vr[it*8+6] * tanh_hw(qr[it*8+6] + f3.x);
                    s0 += vr[it*8+7] * tanh_hw(qr[it*8+7] + f3.y);
                }
#pragma unroll
                for (int o = 16; o; o >>= 1) s0 += __shfl_xor_sync(0xffffffffu, s0, o);
                if (!lane) g_sc[b * 256 + tt] = s0;
            }
        }
        grid_bar();

        // ---- phase 3: softmax (redundant) + ctx for (b, uhalf) ----
        {
            const int b = bid >> 1, uhalf = bid & 1;
            float v = g_sc[b * 256 + tid];
            float m = v;
#pragma unroll
            for (int o = 16; o; o >>= 1) m = fmaxf(m, __shfl_xor_sync(0xffffffffu, m, o));
            if (!lane) red[warp] = m;
            __syncthreads();
            float bm = red[0];
#pragma unroll
            for (int w2 = 1; w2 < 8; w2++) bm = fmaxf(bm, red[w2]);
            __syncthreads();
            float e = __expf(v - bm);
            float ss = e;
#pragma unroll
            for (int o = 16; o; o >>= 1) ss += __shfl_xor_sync(0xffffffffu, ss, o);
            if (!lane) red[warp] = ss;
            __syncthreads();
            float bs = 0.f;
#pragma unroll
            for (int w2 = 0; w2 < 8; w2++) bs += red[w2];
            sm[tid] = __fdividef(e, bs);
            __syncthreads();

            const int u0 = uhalf * 512 + tid * 2;
            const __half2* xb = (const __half2*)(g_xh + (size_t)b * 256 * 1024 + u0);
            float ax = 0.f, ay = 0.f;
#pragma unroll 8
            for (int t = 0; t < 256; t++) {
                float2 xv = __half22float2(xb[(size_t)t * 512]);
                float wt = sm[t];
                ax = fmaf(wt, xv.x, ax);
                ay = fmaf(wt, xv.y, ay);
            }
            pack_a(g_cpk, b, u0, ax, ay);
            __syncthreads();
        }
        grid_bar();

        // ---- phase 4: zp[kh] = ctx @ Wk (64 tiles x 64 cols, split-K2) ----
        {
            const int tile = bid & 63, kh = bid >> 6;
            gtile<4>(cpk_u4, wpk2_u4, &g_zp[kh][0][0], N2, tile * 64, kh, sA, sB);
        }
        grid_bar();

        // ---- phase 5: LSTM gates + state + projection for (b2, jhalf) ----
        {
            const int b2 = bid >> 1, jhalf = bid & 1;
            const int j0 = jhalf * 512 + tid * 2;
            const float* z0 = g_zp[0][b2]; const float* z1 = g_zp[1][b2];
            const float* h0 = g_qp[0][b2] + 1024; const float* h1 = g_qp[1][b2] + 1024;
            float2 a0, a1, c0, c1;
            a0 = *(const float2*)&z0[j0];        a1 = *(const float2*)&z1[j0];
            c0 = *(const float2*)&h0[j0];        c1 = *(const float2*)&h1[j0];
            float2 zi = { bl[j0]   + a0.x + a1.x + c0.x + c1.x,
                          bl[j0+1] + a0.y + a1.y + c0.y + c1.y };
            a0 = *(const float2*)&z0[1024+j0];   a1 = *(const float2*)&z1[1024+j0];
            c0 = *(const float2*)&h0[1024+j0];   c1 = *(const float2*)&h1[1024+j0];
            float2 zf = { bl[1024+j0]   + a0.x + a1.x + c0.x + c1.x,
                          bl[1024+j0+1] + a0.y + a1.y + c0.y + c1.y };
            a0 = *(const float2*)&z0[2048+j0];   a1 = *(const float2*)&z1[2048+j0];
            c0 = *(const float2*)&h0[2048+j0];   c1 = *(const float2*)&h1[2048+j0];
            float2 zg = { bl[2048+j0]   + a0.x + a1.x + c0.x + c1.x,
                          bl[2048+j0+1] + a0.y + a1.y + c0.y + c1.y };
            a0 = *(const float2*)&z0[3072+j0];   a1 = *(const float2*)&z1[3072+j0];
            c0 = *(const float2*)&h0[3072+j0];   c1 = *(const float2*)&h1[3072+j0];
            float2 zo = { bl[3072+j0]   + a0.x + a1.x + c0.x + c1.x,
                          bl[3072+j0+1] + a0.y + a1.y + c0.y + c1.y };

            float2 cold = *(const float2*)&g_c[b2 * 1024 + j0];
            float cx = sigf(zf.x) * cold.x + sigf(zi.x) * fast_tanh(zg.x);
            float cy = sigf(zf.y) * cold.y + sigf(zi.y) * fast_tanh(zg.y);
            float hx = sigf(zo.x) * fast_tanh(cx);
            float hy = sigf(zo.y) * fast_tanh(cy);
            *(float2*)&g_c[b2 * 1024 + j0] = make_float2(cx, cy);
            pack_a(g_hpk, b2, j0, hx, hy);

            float p = hx * Wo[j0] + hy * Wo[j0 + 1];
            if (tid == 0 && jhalf == 0) p += bo[0];
#pragma unroll
            for (int o = 16; o; o >>= 1) p += __shfl_xor_sync(0xffffffffu, p, o);
            if (!lane) red[warp] = p;
            __syncthreads();
            if (tid == 0) {
                float acc = 0.f;
#pragma unroll
                for (int w2 = 0; w2 < 8; w2++) acc += red[w2];
                atomicAdd(&out[s * 64 + b2], acc);
            }
            __syncthreads();
        }
        grid_bar();
    }
}

// ---------------- host launcher ----------------
extern "C" void kernel_launch(void* const* d_in, const int* in_sizes, int n_in,
                              void* d_out, int out_size)
{
    const float* inputs = (const float*)d_in[0];
    const float* We1 = (const float*)d_in[1];  const float* be1 = (const float*)d_in[2];
    const float* We2 = (const float*)d_in[3];  const float* be2 = (const float*)d_in[4];
    const float* W1  = (const float*)d_in[5];  const float* b1  = (const float*)d_in[6];
    const float* W2  = (const float*)d_in[7];  const float* b2k = (const float*)d_in[8];
    const float* V   = (const float*)d_in[9];  /* bV shift-invariant in softmax */
    const float* Wk  = (const float*)d_in[11]; const float* Wr  = (const float*)d_in[12];
    const float* bl  = (const float*)d_in[13]; const float* Wo  = (const float*)d_in[14];
    const float* bo  = (const float*)d_in[15];
    float* out = (float*)d_out;

    void *p_h1pk, *p_xpk, *p_xh, *p_keh, *p_We2pk, *p_W2pk;
    cudaGetSymbolAddress(&p_h1pk,  g_h1pk);
    cudaGetSymbolAddress(&p_xpk,   g_xpk);
    cudaGetSymbolAddress(&p_xh,    g_xh);
    cudaGetSymbolAddress(&p_keh,   g_keh);
    cudaGetSymbolAddress(&p_We2pk, g_We2pk);
    cudaGetSymbolAddress(&p_W2pk,  g_W2pk);

    const int DYN_SMEM = (4096 + 5120) * 16;   // 144 KB: sA 64K + sB 80K
    static int attr_set = 0;
    if (!attr_set) {
        cudaFuncSetAttribute(decode_persistent,
                             cudaFuncAttributeMaxDynamicSharedMemorySize, DYN_SMEM);
        attr_set = 1;
    }

    pack_weights<<<5632, 512>>>(W1, Wr, Wk, We2, W2);
    sgemm128_pack<<<dim3(UU / 128, NROW / 128), 256>>>(inputs, We1, be1, UU, DINN);
    hgemm_big<<<(NROW / 64) * (UU / 32), 256>>>(
        (const __nv_bfloat16*)p_h1pk, (const __nv_bfloat16*)p_We2pk, be2, 1, UU,
        (__nv_bfloat16*)p_xpk, (__half*)p_xh);
    hgemm_big<<<(NROW / 64) * (UU / 32), 256>>>(
        (const __nv_bfloat16*)p_xpk, (const __nv_bfloat16*)p_W2pk, b2k, 0, UU,
        (__nv_bfloat16*)0, (__half*)p_keh);
    init_state<<<64, 1024>>>(out);
    decode_persistent<<<NB, 256, DYN_SMEM>>>(b1, V, bl, Wo, bo, out);
}

// round 15
// speedup vs baseline: 1.2621x; 1.0977x over previous
#include <cuda_runtime.h>
#include <cuda_bf16.h>
#include <cuda_fp16.h>
#include <math.h>

#define BB   64
#define TT   256
#define DINN 128
#define UU   1024
#define SEQ  256
#define NROW (BB*TT)
#define NB   128
#define N1   5120       // [W1 | Wr]
#define N2   4096       // Wk

// ---------------- device scratch ----------------
__device__ __nv_bfloat16 g_h1pk[(size_t)NROW * UU * 2];   // h1 A-frags (KT=64)
__device__ __nv_bfloat16 g_xpk [(size_t)NROW * UU * 2];   // x  A-frags (KT=64)
__device__ __half g_xh [(size_t)NROW * UU];               // x  fp16 linear
__device__ __half g_keh[(size_t)NROW * UU];               // keys fp16 linear
__device__ __nv_bfloat16 g_Wpk1 [(size_t)UU * N1 * 2];    // B-frags [W1|Wr]
__device__ __nv_bfloat16 g_Wpk2 [(size_t)UU * N2 * 2];    // B-frags Wk
__device__ __nv_bfloat16 g_We2pk[(size_t)UU * UU * 2];
__device__ __nv_bfloat16 g_W2pk [(size_t)UU * UU * 2];
__device__ __nv_bfloat16 g_hpk[BB * UU * 2];              // A-frags h
__device__ __nv_bfloat16 g_cpk[BB * UU * 2];              // A-frags ctx
__device__ float g_qp[2][BB][N1];                         // split-K partials
__device__ float g_zp[2][BB][N2];
__device__ float g_c [BB * UU];
__device__ float g_sc[BB * TT];
__device__ unsigned g_bar_cnt = 0;
__device__ unsigned g_bar_gen = 0;
__device__ unsigned g_qcnt   = 0;
__device__ unsigned g_pair[BB * 32];   // per-batch pair counters (128B padded)

// ---------------- helpers ----------------
__device__ __forceinline__ float tanh_hw(float x) {
    float y; asm("tanh.approx.f32 %0, %1;" : "=f"(y) : "f"(x)); return y;
}
__device__ __forceinline__ float fast_tanh(float x) {
    float e = __expf(2.0f * x);
    return 1.0f - __fdividef(2.0f, e + 1.0f);
}
__device__ __forceinline__ float sigf(float x) {
    return __fdividef(1.0f, 1.0f + __expf(-x));
}
__device__ __forceinline__ void mma16816(float d[4], const uint4& a, const uint2& b) {
    asm("mma.sync.aligned.m16n8k16.row.col.f32.bf16.bf16.f32 "
        "{%0,%1,%2,%3},{%4,%5,%6,%7},{%8,%9},{%0,%1,%2,%3};"
        : "+f"(d[0]), "+f"(d[1]), "+f"(d[2]), "+f"(d[3])
        : "r"(a.x), "r"(a.y), "r"(a.z), "r"(a.w), "r"(b.x), "r"(b.y));
}
__device__ __forceinline__ void cp16(void* smem, const void* g) {
    unsigned s = (unsigned)__cvta_generic_to_shared(smem);
    asm volatile("cp.async.cg.shared.global [%0], [%1], 16;" :: "r"(s), "l"(g));
}
__device__ __forceinline__ void cp_commit() {
    asm volatile("cp.async.commit_group;");
}
template<int N> __device__ __forceinline__ void cp_wait() {
    asm volatile("cp.async.wait_group %0;" :: "n"(N));
}

// flat grid barrier (R9-proven): acq_rel arrival, release gen-add, acquire spin
__device__ __forceinline__ void grid_bar() {
    __syncthreads();
    if (threadIdx.x == 0) {
        unsigned gen;
        asm volatile("ld.acquire.gpu.u32 %0, [%1];" : "=r"(gen) : "l"(&g_bar_gen));
        unsigned prev;
        asm volatile("atom.acq_rel.gpu.add.u32 %0, [%1], 1;"
                     : "=r"(prev) : "l"(&g_bar_cnt));
        if (prev == NB - 1) {
            asm volatile("st.relaxed.gpu.u32 [%0], 0;" :: "l"(&g_bar_cnt));
            unsigned d;
            asm volatile("atom.add.release.gpu.u32 %0, [%1], 1;"
                         : "=r"(d) : "l"(&g_bar_gen));
        } else {
            unsigned g;
            do {
                asm volatile("ld.acquire.gpu.u32 %0, [%1];" : "=r"(g) : "l"(&g_bar_gen));
            } while (g == gen);
        }
    }
    __syncthreads();
}

// ---------------- split + A-fragment pack ----------------
__device__ __forceinline__ void split_bf16(float v, __nv_bfloat16& hi, __nv_bfloat16& lo) {
    hi = __float2bfloat16(v);
    lo = __float2bfloat16(v - __bfloat162float(hi));
}
__device__ __forceinline__ void pack_a(__nv_bfloat16* dst, int row, int u,
                                       float vx, float vy)
{
    const int mt = row >> 4, rm = row & 15;
    const int kt = u >> 4,  cm = u & 15;          // u even
    const int lane = (rm & 7) * 4 + ((cm & 7) >> 1);
    const int reg  = (rm >> 3) + ((cm >> 3) & 1) * 2;
    const size_t base = ((size_t)(mt * 64 + kt) * 32 + lane) * 16;
    __nv_bfloat16 hx, lx, hy, ly;
    split_bf16(vx, hx, lx);
    split_bf16(vy, hy, ly);
    __nv_bfloat162 hp; hp.x = hx; hp.y = hy;
    __nv_bfloat162 lp; lp.x = lx; lp.y = ly;
    *(__nv_bfloat162*)&dst[base + reg * 2]     = hp;
    *(__nv_bfloat162*)&dst[base + 8 + reg * 2] = lp;
}

// ---------------- GEMM1 (fp32 SIMT, K=128): h1pk = pack(relu(inputs@We1+be1)) ----
__global__ __launch_bounds__(256, 2)
void sgemm128_pack(const float* __restrict__ A, const float* __restrict__ Bm,
                   const float* __restrict__ bias, int N, int K)
{
    __shared__ float As[8][128];
    __shared__ float Bs[8][128];
    const int tid  = threadIdx.x;
    const int brow = blockIdx.y, bcol = blockIdx.x;
    const int tr = tid >> 4, tc = tid & 15;
    const int aRow = tid >> 1, aCol = (tid & 1) * 4;
    const int bRow = tid >> 5, bCol = (tid & 31) * 4;
    const float* Ap = A + (size_t)(brow * 128) * K;
    const float* Bp = Bm + bcol * 128;

    float acc[8][8];
#pragma unroll
    for (int i = 0; i < 8; i++)
#pragma unroll
        for (int j = 0; j < 8; j++) acc[i][j] = 0.f;

    for (int k0 = 0; k0 < K; k0 += 8) {
        float4 av = *(const float4*)(Ap + (size_t)aRow * K + k0 + aCol);
        As[aCol + 0][aRow] = av.x; As[aCol + 1][aRow] = av.y;
        As[aCol + 2][aRow] = av.z; As[aCol + 3][aRow] = av.w;
        float4 bv = *(const float4*)(Bp + (size_t)(k0 + bRow) * N + bCol);
        *(float4*)&Bs[bRow][bCol] = bv;
        __syncthreads();
#pragma unroll
        for (int kk = 0; kk < 8; kk++) {
            float4 a0 = *(const float4*)&As[kk][tr * 8];
            float4 a1 = *(const float4*)&As[kk][tr * 8 + 4];
            float4 b0 = *(const float4*)&Bs[kk][tc * 8];
            float4 b1 = *(const float4*)&Bs[kk][tc * 8 + 4];
            float ar[8] = {a0.x,a0.y,a0.z,a0.w,a1.x,a1.y,a1.z,a1.w};
            float br[8] = {b0.x,b0.y,b0.z,b0.w,b1.x,b1.y,b1.z,b1.w};
#pragma unroll
            for (int i = 0; i < 8; i++)
#pragma unroll
                for (int j = 0; j < 8; j++)
                    acc[i][j] = fmaf(ar[i], br[j], acc[i][j]);
        }
        __syncthreads();
    }
#pragma unroll
    for (int i = 0; i < 8; i++) {
        int row = brow * 128 + tr * 8 + i;
#pragma unroll
        for (int j = 0; j < 8; j += 2) {
            int col = bcol * 128 + tc * 8 + j;
            float v0 = fmaxf(acc[i][j]     + bias[col],     0.f);
            float v1 = fmaxf(acc[i][j + 1] + bias[col + 1], 0.f);
            pack_a(g_h1pk, row, col, v0, v1);
        }
    }
}

// ---------------- pack weights into split B-fragment layout ----------------
__global__ void pack_weights(const float* __restrict__ W1, const float* __restrict__ Wr,
                             const float* __restrict__ Wk, const float* __restrict__ We2,
                             const float* __restrict__ W2)
{
    const int TOT1 = (N1 / 8) * 64 * 32;
    const int TOT2 = (N2 / 8) * 64 * 32;
    const int TOT3 = (UU / 8) * 64 * 32;
    int c = blockIdx.x * blockDim.x + threadIdx.x;
    float w[4];
    __nv_bfloat16* o;
    if (c < TOT1) {
        int cl = c;
        int nt8 = cl / 2048, rem = cl % 2048, kt = rem >> 5, l = rem & 31;
        int n  = nt8 * 8 + (l >> 2);
        int k0 = kt * 16 + (l & 3) * 2;
        const float* W; int ld, nn;
        if (n < 1024) { W = W1; ld = 1024; nn = n; }
        else          { W = Wr; ld = 4096; nn = n - 1024; }
        w[0] = W[(size_t)(k0    ) * ld + nn];
        w[1] = W[(size_t)(k0 + 1) * ld + nn];
        w[2] = W[(size_t)(k0 + 8) * ld + nn];
        w[3] = W[(size_t)(k0 + 9) * ld + nn];
        o = g_Wpk1 + (size_t)cl * 8;
    } else if (c < TOT1 + TOT2) {
        int cl = c - TOT1;
        int nt8 = cl / 2048, rem = cl % 2048, kt = rem >> 5, l = rem & 31;
        int n  = nt8 * 8 + (l >> 2);
        int k0 = kt * 16 + (l & 3) * 2;
        w[0] = Wk[(size_t)(k0    ) * 4096 + n];
        w[1] = Wk[(size_t)(k0 + 1) * 4096 + n];
        w[2] = Wk[(size_t)(k0 + 8) * 4096 + n];
        w[3] = Wk[(size_t)(k0 + 9) * 4096 + n];
        o = g_Wpk2 + (size_t)cl * 8;
    } else if (c < TOT1 + TOT2 + 2 * TOT3) {
        int cl = c - TOT1 - TOT2;
        const float* W = We2;
        __nv_bfloat16* dst = g_We2pk;
        if (cl >= TOT3) { cl -= TOT3; W = W2; dst = g_W2pk; }
        int nt8 = cl / 2048, rem = cl % 2048, kt = rem >> 5, l = rem & 31;
        int n  = nt8 * 8 + (l >> 2);
        int k0 = kt * 16 + (l & 3) * 2;
        w[0] = W[(size_t)(k0    ) * 1024 + n];
        w[1] = W[(size_t)(k0 + 1) * 1024 + n];
        w[2] = W[(size_t)(k0 + 8) * 1024 + n];
        w[3] = W[(size_t)(k0 + 9) * 1024 + n];
        o = dst + (size_t)cl * 8;
    } else return;
#pragma unroll
    for (int i = 0; i < 4; i++) split_bf16(w[i], o[i], o[4 + i]);
}

// ---------------- big split-bf16 HMMA (precompute) ----------------
__global__ __launch_bounds__(256)
void hgemm_big(const __nv_bfloat16* __restrict__ Apk,
               const __nv_bfloat16* __restrict__ Wpk,
               const float* __restrict__ bias, int doRelu, int N,
               __nv_bfloat16* __restrict__ outPk, __half* __restrict__ outH)
{
    const int tiles_n = N / 32;
    const int tm = blockIdx.x / tiles_n, tn = blockIdx.x % tiles_n;
    const int tid = threadIdx.x;
    const int w = tid >> 5, l = tid & 31;
    const int mt = w >> 1, np = w & 1;
    const int mtg = tm * 4 + mt;
    const uint4* a_it  = (const uint4*)Apk + ((size_t)mtg * 2048 + l) * 2;
    const int nt0 = tn * 4 + np * 2;
    const uint4* b0_it = (const uint4*)Wpk + (size_t)nt0 * 2048 + l;
    const uint4* b1_it = b0_it + 2048;

    float d0[4] = {0.f,0.f,0.f,0.f};
    float d1[4] = {0.f,0.f,0.f,0.f};
#pragma unroll 4
    for (int kt = 0; kt < 64; kt++) {
        uint4 aH = a_it[(size_t)kt * 64];
        uint4 aL = a_it[(size_t)kt * 64 + 1];
        uint4 b0 = b0_it[kt * 32];
        uint4 b1 = b1_it[kt * 32];
        uint2 b0H = make_uint2(b0.x, b0.y), b0L = make_uint2(b0.z, b0.w);
        uint2 b1H = make_uint2(b1.x, b1.y), b1L = make_uint2(b1.z, b1.w);
        mma16816(d0, aH, b0H);
        mma16816(d0, aH, b0L);
        mma16816(d0, aL, b0H);
        mma16816(d1, aH, b1H);
        mma16816(d1, aH, b1L);
        mma16816(d1, aL, b1H);
    }
    const int r0 = tm * 64 + mt * 16 + (l >> 2);
    const int c0 = tn * 32 + np * 16 + ((l & 3) << 1);
    float2 bbA = *(const float2*)&bias[c0];
    float2 bbB = *(const float2*)&bias[c0 + 8];
    d0[0] += bbA.x; d0[1] += bbA.y; d0[2] += bbA.x; d0[3] += bbA.y;
    d1[0] += bbB.x; d1[1] += bbB.y; d1[2] += bbB.x; d1[3] += bbB.y;
    if (doRelu) {
#pragma unroll
        for (int i = 0; i < 4; i++) {
            d0[i] = fmaxf(d0[i], 0.f);
            d1[i] = fmaxf(d1[i], 0.f);
        }
    }
    if (outH) {
        *(__half2*)&outH[(size_t)r0 * N + c0]           = __floats2half2_rn(d0[0], d0[1]);
        *(__half2*)&outH[(size_t)(r0 + 8) * N + c0]     = __floats2half2_rn(d0[2], d0[3]);
        *(__half2*)&outH[(size_t)r0 * N + c0 + 8]       = __floats2half2_rn(d1[0], d1[1]);
        *(__half2*)&outH[(size_t)(r0 + 8) * N + c0 + 8] = __floats2half2_rn(d1[2], d1[3]);
    }
    if (outPk) {
        pack_a(outPk, r0,     c0,     d0[0], d0[1]);
        pack_a(outPk, r0 + 8, c0,     d0[2], d0[3]);
        pack_a(outPk, r0,     c0 + 8, d1[0], d1[1]);
        pack_a(outPk, r0 + 8, c0 + 8, d1[2], d1[3]);
    }
}

// ---------------- init ----------------
__global__ void init_state(float* __restrict__ out)
{
    int idx = blockIdx.x * blockDim.x + threadIdx.x;
    if (idx < BB * UU) {
        g_c[idx] = 0.f;
        g_hpk[idx] = __float2bfloat16(0.f);
        g_hpk[BB * UU + idx] = __float2bfloat16(0.f);
    }
    if (idx < SEQ * BB) out[idx] = 0.f;
    if (idx < BB * 32) g_pair[idx] = 0;
    if (idx == 0) { g_bar_cnt = 0; g_qcnt = 0; }
}

// ---------------- smem-staged 64xN step-GEMM task (split-K half) ----------
template<int NJ>   // NJ = nt8 per warp (tile N = 16*NJ); NJ=5 -> 80 cols, NJ=4 -> 64
__device__ __forceinline__ void gtile(const uint4* __restrict__ Apk,
                                      const uint4* __restrict__ Wpk,
                                      float* __restrict__ C, int ldc,
                                      int n0, int khalf,
                                      uint4* sA, uint4* sB)
{
    constexpr int NT = 2 * NJ;
    const int tid = threadIdx.x;
    const int w = tid >> 5, l = tid & 31;
    const int mt = w >> 1, np = w & 1;
    const int nt8base = n0 >> 3;
    const int ktbase = khalf * 32;

    float d[NJ][4];
#pragma unroll
    for (int j = 0; j < NJ; j++)
#pragma unroll
        for (int i = 0; i < 4; i++) d[j][i] = 0.f;

    auto load = [&](int buf, int cix) {
        const int kt0 = ktbase + cix * 8;
#pragma unroll
        for (int i = tid; i < 1024; i += 256) {
            int lane = i & 31, mtt = (i >> 5) & 3, ktl = i >> 7;
            const uint4* src = Apk + ((size_t)(mtt * 64 + kt0 + ktl) * 32 + lane) * 2;
            cp16(&sA[(((buf * 2 + 0) * 8 + ktl) * 4 + mtt) * 32 + lane], src);
            cp16(&sA[(((buf * 2 + 1) * 8 + ktl) * 4 + mtt) * 32 + lane], src + 1);
        }
        for (int i = tid; i < NT * 8 * 32; i += 256) {
            int lane = i & 31, nt = (i >> 5) % NT, ktl = (i >> 5) / NT;
            const uint4* src = Wpk + (size_t)((nt8base + nt) * 64 + kt0 + ktl) * 32 + lane;
            cp16(&sB[((buf * 8 + ktl) * NT + nt) * 32 + lane], src);
        }
        cp_commit();
    };

    load(0, 0);
    for (int c = 0; c < 4; c++) {
        if (c < 3) { load((c + 1) & 1, c + 1); cp_wait<1>(); }
        else       { cp_wait<0>(); }
        __syncthreads();
        const int buf = c & 1;
#pragma unroll
        for (int ktl = 0; ktl < 8; ktl++) {
            uint4 aH = sA[(((buf * 2 + 0) * 8 + ktl) * 4 + mt) * 32 + l];
            uint4 aL = sA[(((buf * 2 + 1) * 8 + ktl) * 4 + mt) * 32 + l];
#pragma unroll
            for (int j = 0; j < NJ; j++) {
                uint4 b = sB[((buf * 8 + ktl) * NT + np * NJ + j) * 32 + l];
                uint2 bH = make_uint2(b.x, b.y), bL = make_uint2(b.z, b.w);
                mma16816(d[j], aH, bH);
                mma16816(d[j], aH, bL);
                mma16816(d[j], aL, bH);
            }
        }
        __syncthreads();
    }
    const int r0 = mt * 16 + (l >> 2);
#pragma unroll
    for (int j = 0; j < NJ; j++) {
        const int c0 = n0 + (np * NJ + j) * 8 + ((l & 3) << 1);
        *(float2*)&C[(size_t)r0 * ldc + c0]       = make_float2(d[j][0], d[j][1]);
        *(float2*)&C[(size_t)(r0 + 8) * ldc + c0] = make_float2(d[j][2], d[j][3]);
    }
}

// ---------------- persistent decode (q-flag + pair-sync + 3 full bars) -----
extern __shared__ uint4 dynsm[];
__global__ __launch_bounds__(256, 1)
void decode_persistent(const float* __restrict__ b1, const float* __restrict__ V,
                       const float* __restrict__ bl, const float* __restrict__ Wo,
                       const float* __restrict__ bo, float* __restrict__ out)
{
    __shared__ float sm[256];
    __shared__ float red[8];
    uint4* sA = dynsm;          // 4096 uint4 = 64 KB
    uint4* sB = dynsm + 4096;   // up to 5120 uint4 = 80 KB
    const int tid  = threadIdx.x;
    const int bid  = blockIdx.x;
    const int warp = tid >> 5, lane = tid & 31;

    const uint4* hpk_u4  = (const uint4*)g_hpk;
    const uint4* cpk_u4  = (const uint4*)g_cpk;
    const uint4* wpk1_u4 = (const uint4*)g_Wpk1;
    const uint4* wpk2_u4 = (const uint4*)g_Wpk2;

    for (int s = 0; s < SEQ; s++) {
        // ---- phase 1: qp[kh] = h @ [W1|Wr]; q-tiles first + release flag ----
        // q-tasks: bids 0..25 -> tiles 0..12 (cols 0..1039) x kh
        // hr-tasks: bids 26..127 -> tiles 13..63 (51 tiles) x kh = 102 tasks
        {
            int tile, kh;
            if (bid < 26) { tile = bid >> 1;            kh = bid & 1; }
            else          { int t = bid - 26; tile = 13 + (t >> 1); kh = t & 1; }
            gtile<5>(hpk_u4, wpk1_u4, &g_qp[kh][0][0], N1, tile * 80, kh, sA, sB);
            if (bid < 26) {
                __syncthreads();
                if (tid == 0) {
                    unsigned d;
                    asm volatile("atom.add.release.gpu.u32 %0, [%1], 1;"
                                 : "=r"(d) : "l"(&g_qcnt));
                }
            }
        }
        // wait for all 26 q-tasks of this step
        {
            __syncthreads();
            if (tid == 0) {
                const unsigned tgt = 26u * (unsigned)(s + 1);
                unsigned g;
                do {
                    asm volatile("ld.acquire.gpu.u32 %0, [%1];" : "=r"(g) : "l"(&g_qcnt));
                } while (g < tgt);
            }
            __syncthreads();
        }

        // ---- phase 2: scores for (b, thalf) ----
        const int b2s = bid >> 1;
        {
            const int b = b2s, thalf = bid & 1;
            float qr[32], vr[32];
#pragma unroll
            for (int it = 0; it < 4; it++) {
                const int base = it * 256 + lane * 8;
#pragma unroll
                for (int k2 = 0; k2 < 8; k2 += 4) {
                    float4 q0 = *(const float4*)&g_qp[0][b][base + k2];
                    float4 q1 = *(const float4*)&g_qp[1][b][base + k2];
                    float4 bb = *(const float4*)&b1[base + k2];
                    float4 vv = *(const float4*)&V[base + k2];
                    qr[it*8+k2+0] = q0.x + q1.x + bb.x;  vr[it*8+k2+0] = vv.x;
                    qr[it*8+k2+1] = q0.y + q1.y + bb.y;  vr[it*8+k2+1] = vv.y;
                    qr[it*8+k2+2] = q0.z + q1.z + bb.z;  vr[it*8+k2+2] = vv.z;
                    qr[it*8+k2+3] = q0.w + q1.w + bb.w;  vr[it*8+k2+3] = vv.w;
                }
            }
            for (int t = warp; t < 128; t += 8) {
                const int tt = thalf * 128 + t;
                const uint4* kp = (const uint4*)(g_keh + ((size_t)(b * 256 + tt)) * 1024);
                float s0 = 0.f;
#pragma unroll
                for (int it = 0; it < 4; it++) {
                    uint4 kv = kp[it * 32 + lane];
                    float2 f0 = __half22float2(*(__half2*)&kv.x);
                    float2 f1 = __half22float2(*(__half2*)&kv.y);
                    float2 f2 = __half22float2(*(__half2*)&kv.z);
                    float2 f3 = __half22float2(*(__half2*)&kv.w);
                    s0 += vr[it*8+0] * tanh_hw(qr[it*8+0] + f0.x);
                    s0 += vr[it*8+1] * tanh_hw(qr[it*8+1] + f0.y);
                    s0 += vr[it*8+2] * tanh_hw(qr[it*8+2] + f1.x);
                    s0 += vr[it*8+3] * tanh_hw(qr[it*8+3] + f1.y);
                    s0 += vr[it*8+4] * tanh_hw(qr[it*8+4] + f2.x);
                    s0 += vr[it*8+5] * tanh_hw(qr[it*8+5] + f2.y);
                    s0 += vr[it*8+6] * tanh_hw(qr[it*8+6] + f3.x);
                    s0 += vr[it*8+7] * tanh_hw(qr[it*8+7] + f3.y);
                }
#pragma unroll
                for (int o = 16; o; o >>= 1) s0 += __shfl_xor_sync(0xffffffffu, s0, o);
                if (!lane) g_sc[b * 256 + tt] = s0;
            }
        }
        // pairwise sync: blocks (2b, 2b+1) exchange score halves
        {
            __syncthreads();
            if (tid == 0) {
                unsigned d;
                asm volatile("atom.add.release.gpu.u32 %0, [%1], 1;"
                             : "=r"(d) : "l"(&g_pair[b2s * 32]));
                const unsigned tgt = 2u * (unsigned)(s + 1);
                unsigned g;
                do {
                    asm volatile("ld.acquire.gpu.u32 %0, [%1];"
                                 : "=r"(g) : "l"(&g_pair[b2s * 32]));
                } while (g < tgt);
            }
            __syncthreads();
        }

        // ---- phase 3: softmax (redundant in pair) + ctx for (b, uhalf) ----
        {
            const int b = bid >> 1, uhalf = bid & 1;
            float v = g_sc[b * 256 + tid];
            float m = v;
#pragma unroll
            for (int o = 16; o; o >>= 1) m = fmaxf(m, __shfl_xor_sync(0xffffffffu, m, o));
            if (!lane) red[warp] = m;
            __syncthreads();
            float bm = red[0];
#pragma unroll
            for (int w2 = 1; w2 < 8; w2++) bm = fmaxf(bm, red[w2]);
            __syncthreads();
            float e = __expf(v - bm);
            float ss = e;
#pragma unroll
            for (int o = 16; o; o >>= 1) ss += __shfl_xor_sync(0xffffffffu, ss, o);
            if (!lane) red[warp] = ss;
            __syncthreads();
            float bs = 0.f;
#pragma unroll
            for (int w2 = 0; w2 < 8; w2++) bs += red[w2];
            sm[tid] = __fdividef(e, bs);
            __syncthreads();

            const int u0 = uhalf * 512 + tid * 2;
            const __half2* xb = (const __half2*)(g_xh + (size_t)b * 256 * 1024 + u0);
            float ax = 0.f, ay = 0.f;
#pragma unroll 8
            for (int t = 0; t < 256; t++) {
                float2 xv = __half22float2(xb[(size_t)t * 512]);
                float wt = sm[t];
                ax = fmaf(wt, xv.x, ax);
                ay = fmaf(wt, xv.y, ay);
            }
            pack_a(g_cpk, b, u0, ax, ay);
            __syncthreads();
        }
        grid_bar();   // all ctx (and hr, by program order) published

        // ---- phase 4: zp[kh] = ctx @ Wk (64 tiles x 64 cols, split-K2) ----
        {
            const int tile = bid & 63, kh = bid >> 6;
            gtile<4>(cpk_u4, wpk2_u4, &g_zp[kh][0][0], N2, tile * 64, kh, sA, sB);
        }
        grid_bar();

        // ---- phase 5: LSTM gates + state + projection for (b2, jhalf) ----
        {
            const int b2 = bid >> 1, jhalf = bid & 1;
            const int j0 = jhalf * 512 + tid * 2;
            const float* z0 = g_zp[0][b2]; const float* z1 = g_zp[1][b2];
            const float* h0 = g_qp[0][b2] + 1024; const float* h1 = g_qp[1][b2] + 1024;
            float2 a0, a1, c0, c1;
            a0 = *(const float2*)&z0[j0];        a1 = *(const float2*)&z1[j0];
            c0 = *(const float2*)&h0[j0];        c1 = *(const float2*)&h1[j0];
            float2 zi = { bl[j0]   + a0.x + a1.x + c0.x + c1.x,
                          bl[j0+1] + a0.y + a1.y + c0.y + c1.y };
            a0 = *(const float2*)&z0[1024+j0];   a1 = *(const float2*)&z1[1024+j0];
            c0 = *(const float2*)&h0[1024+j0];   c1 = *(const float2*)&h1[1024+j0];
            float2 zf = { bl[1024+j0]   + a0.x + a1.x + c0.x + c1.x,
                          bl[1024+j0+1] + a0.y + a1.y + c0.y + c1.y };
            a0 = *(const float2*)&z0[2048+j0];   a1 = *(const float2*)&z1[2048+j0];
            c0 = *(const float2*)&h0[2048+j0];   c1 = *(const float2*)&h1[2048+j0];
            float2 zg = { bl[2048+j0]   + a0.x + a1.x + c0.x + c1.x,
                          bl[2048+j0+1] + a0.y + a1.y + c0.y + c1.y };
            a0 = *(const float2*)&z0[3072+j0];   a1 = *(const float2*)&z1[3072+j0];
            c0 = *(const float2*)&h0[3072+j0];   c1 = *(const float2*)&h1[3072+j0];
            float2 zo = { bl[3072+j0]   + a0.x + a1.x + c0.x + c1.x,
                          bl[3072+j0+1] + a0.y + a1.y + c0.y + c1.y };

            float2 cold = *(const float2*)&g_c[b2 * 1024 + j0];
            float cx = sigf(zf.x) * cold.x + sigf(zi.x) * fast_tanh(zg.x);
            float cy = sigf(zf.y) * cold.y + sigf(zi.y) * fast_tanh(zg.y);
            float hx = sigf(zo.x) * fast_tanh(cx);
            float hy = sigf(zo.y) * fast_tanh(cy);
            *(float2*)&g_c[b2 * 1024 + j0] = make_float2(cx, cy);
            pack_a(g_hpk, b2, j0, hx, hy);

            float p = hx * Wo[j0] + hy * Wo[j0 + 1];
            if (tid == 0 && jhalf == 0) p += bo[0];
#pragma unroll
            for (int o = 16; o; o >>= 1) p += __shfl_xor_sync(0xffffffffu, p, o);
            if (!lane) red[warp] = p;
            __syncthreads();
            if (tid == 0) {
                float acc = 0.f;
#pragma unroll
                for (int w2 = 0; w2 < 8; w2++) acc += red[w2];
                atomicAdd(&out[s * 64 + b2], acc);
            }
            __syncthreads();
        }
        grid_bar();
    }
}

// ---------------- host launcher ----------------
extern "C" void kernel_launch(void* const* d_in, const int* in_sizes, int n_in,
                              void* d_out, int out_size)
{
    const float* inputs = (const float*)d_in[0];
    const float* We1 = (const float*)d_in[1];  const float* be1 = (const float*)d_in[2];
    const float* We2 = (const float*)d_in[3];  const float* be2 = (const float*)d_in[4];
    const float* W1  = (const float*)d_in[5];  const float* b1  = (const float*)d_in[6];
    const float* W2  = (const float*)d_in[7];  const float* b2k = (const float*)d_in[8];
    const float* V   = (const float*)d_in[9];  /* bV shift-invariant in softmax */
    const float* Wk  = (const float*)d_in[11]; const float* Wr  = (const float*)d_in[12];
    const float* bl  = (const float*)d_in[13]; const float* Wo  = (const float*)d_in[14];
    const float* bo  = (const float*)d_in[15];
    float* out = (float*)d_out;

    void *p_h1pk, *p_xpk, *p_xh, *p_keh, *p_We2pk, *p_W2pk;
    cudaGetSymbolAddress(&p_h1pk,  g_h1pk);
    cudaGetSymbolAddress(&p_xpk,   g_xpk);
    cudaGetSymbolAddress(&p_xh,    g_xh);
    cudaGetSymbolAddress(&p_keh,   g_keh);
    cudaGetSymbolAddress(&p_We2pk, g_We2pk);
    cudaGetSymbolAddress(&p_W2pk,  g_W2pk);

    const int DYN_SMEM = (4096 + 5120) * 16;   // 144 KB: sA 64K + sB 80K
    static int attr_set = 0;
    if (!attr_set) {
        cudaFuncSetAttribute(decode_persistent,
                             cudaFuncAttributeMaxDynamicSharedMemorySize, DYN_SMEM);
        attr_set = 1;
    }

    pack_weights<<<5632, 512>>>(W1, Wr, Wk, We2, W2);
    sgemm128_pack<<<dim3(UU / 128, NROW / 128), 256>>>(inputs, We1, be1, UU, DINN);
    hgemm_big<<<(NROW / 64) * (UU / 32), 256>>>(
        (const __nv_bfloat16*)p_h1pk, (const __nv_bfloat16*)p_We2pk, be2, 1, UU,
        (__nv_bfloat16*)p_xpk, (__half*)p_xh);
    hgemm_big<<<(NROW / 64) * (UU / 32), 256>>>(
        (const __nv_bfloat16*)p_xpk, (const __nv_bfloat16*)p_W2pk, b2k, 0, UU,
        (__nv_bfloat16*)0, (__half*)p_keh);
    init_state<<<64, 1024>>>(out);
    decode_persistent<<<NB, 256, DYN_SMEM>>>(b1, V, bl, Wo, bo, out);
}

// round 16
// speedup vs baseline: 1.2869x; 1.0196x over previous
#include <cuda_runtime.h>
#include <cuda_bf16.h>
#include <cuda_fp16.h>
#include <math.h>

#define BB   64
#define TT   256
#define DINN 128
#define UU   1024
#define SEQ  256
#define NROW (BB*TT)
#define NB   128
#define N1   5120       // [W1 | Wr]
#define N2   4096       // Wk

// ---------------- device scratch ----------------
__device__ __nv_bfloat16 g_h1pk[(size_t)NROW * UU * 2];   // h1 A-frags (KT=64)
__device__ __nv_bfloat16 g_xpk [(size_t)NROW * UU * 2];   // x  A-frags (KT=64)
__device__ __half g_xh [(size_t)NROW * UU];               // x  fp16 linear
__device__ __half g_keh[(size_t)NROW * UU];               // keys fp16 linear
__device__ __nv_bfloat16 g_Wpk1 [(size_t)UU * N1 * 2];    // B-frags [W1|Wr]
__device__ __nv_bfloat16 g_Wpk2 [(size_t)UU * N2 * 2];    // B-frags Wk
__device__ __nv_bfloat16 g_We2pk[(size_t)UU * UU * 2];
__device__ __nv_bfloat16 g_W2pk [(size_t)UU * UU * 2];
__device__ __nv_bfloat16 g_hpk[BB * UU * 2];              // A-frags h
__device__ __nv_bfloat16 g_cpk[BB * UU * 2];              // A-frags ctx
__device__ float g_qp[2][2][BB][N1];                      // [parity][kh] split-K partials
__device__ float g_zp[2][BB][N2];
__device__ float g_c [BB * UU];
__device__ float g_sc[2][BB * TT];                        // [parity]
__device__ unsigned g_bar_cnt = 0;
__device__ unsigned g_bar_gen = 0;
__device__ unsigned g_qcnt   = 0;
__device__ unsigned g_pair[BB * 32];    // per-batch pair counters (128B padded)
__device__ unsigned g_ctxc[2 * 32];     // per-uhalf ctx counters
__device__ unsigned g_hcnt[2 * 32];     // per-jhalf h counters

// ---------------- helpers ----------------
__device__ __forceinline__ float tanh_hw(float x) {
    float y; asm("tanh.approx.f32 %0, %1;" : "=f"(y) : "f"(x)); return y;
}
__device__ __forceinline__ float fast_tanh(float x) {
    float e = __expf(2.0f * x);
    return 1.0f - __fdividef(2.0f, e + 1.0f);
}
__device__ __forceinline__ float sigf(float x) {
    return __fdividef(1.0f, 1.0f + __expf(-x));
}
__device__ __forceinline__ void mma16816(float d[4], const uint4& a, const uint2& b) {
    asm("mma.sync.aligned.m16n8k16.row.col.f32.bf16.bf16.f32 "
        "{%0,%1,%2,%3},{%4,%5,%6,%7},{%8,%9},{%0,%1,%2,%3};"
        : "+f"(d[0]), "+f"(d[1]), "+f"(d[2]), "+f"(d[3])
        : "r"(a.x), "r"(a.y), "r"(a.z), "r"(a.w), "r"(b.x), "r"(b.y));
}
__device__ __forceinline__ void cp16(void* smem, const void* g) {
    unsigned s = (unsigned)__cvta_generic_to_shared(smem);
    asm volatile("cp.async.cg.shared.global [%0], [%1], 16;" :: "r"(s), "l"(g));
}
__device__ __forceinline__ void cp_commit() {
    asm volatile("cp.async.commit_group;");
}
template<int N> __device__ __forceinline__ void cp_wait() {
    asm volatile("cp.async.wait_group %0;" :: "n"(N));
}

// flat grid barrier (R9-proven)
__device__ __forceinline__ void grid_bar() {
    __syncthreads();
    if (threadIdx.x == 0) {
        unsigned gen;
        asm volatile("ld.acquire.gpu.u32 %0, [%1];" : "=r"(gen) : "l"(&g_bar_gen));
        unsigned prev;
        asm volatile("atom.acq_rel.gpu.add.u32 %0, [%1], 1;"
                     : "=r"(prev) : "l"(&g_bar_cnt));
        if (prev == NB - 1) {
            asm volatile("st.relaxed.gpu.u32 [%0], 0;" :: "l"(&g_bar_cnt));
            unsigned d;
            asm volatile("atom.add.release.gpu.u32 %0, [%1], 1;"
                         : "=r"(d) : "l"(&g_bar_gen));
        } else {
            unsigned g;
            do {
                asm volatile("ld.acquire.gpu.u32 %0, [%1];" : "=r"(g) : "l"(&g_bar_gen));
            } while (g == gen);
        }
    }
    __syncthreads();
}

// counter release (thread0, after __syncthreads) and acquire-spin wait
__device__ __forceinline__ void ctr_release(unsigned* c) {
    __syncthreads();
    if (threadIdx.x == 0) {
        unsigned d;
        asm volatile("atom.add.release.gpu.u32 %0, [%1], 1;" : "=r"(d) : "l"(c));
    }
}
__device__ __forceinline__ void ctr_wait(unsigned* c, unsigned tgt) {
    __syncthreads();
    if (threadIdx.x == 0) {
        unsigned g;
        do {
            asm volatile("ld.acquire.gpu.u32 %0, [%1];" : "=r"(g) : "l"(c));
        } while (g < tgt);
    }
    __syncthreads();
}

// ---------------- split + A-fragment pack ----------------
__device__ __forceinline__ void split_bf16(float v, __nv_bfloat16& hi, __nv_bfloat16& lo) {
    hi = __float2bfloat16(v);
    lo = __float2bfloat16(v - __bfloat162float(hi));
}
__device__ __forceinline__ void pack_a(__nv_bfloat16* dst, int row, int u,
                                       float vx, float vy)
{
    const int mt = row >> 4, rm = row & 15;
    const int kt = u >> 4,  cm = u & 15;          // u even
    const int lane = (rm & 7) * 4 + ((cm & 7) >> 1);
    const int reg  = (rm >> 3) + ((cm >> 3) & 1) * 2;
    const size_t base = ((size_t)(mt * 64 + kt) * 32 + lane) * 16;
    __nv_bfloat16 hx, lx, hy, ly;
    split_bf16(vx, hx, lx);
    split_bf16(vy, hy, ly);
    __nv_bfloat162 hp; hp.x = hx; hp.y = hy;
    __nv_bfloat162 lp; lp.x = lx; lp.y = ly;
    *(__nv_bfloat162*)&dst[base + reg * 2]     = hp;
    *(__nv_bfloat162*)&dst[base + 8 + reg * 2] = lp;
}

// ---------------- GEMM1 (fp32 SIMT, K=128): h1pk = pack(relu(inputs@We1+be1)) ----
__global__ __launch_bounds__(256, 2)
void sgemm128_pack(const float* __restrict__ A, const float* __restrict__ Bm,
                   const float* __restrict__ bias, int N, int K)
{
    __shared__ float As[8][128];
    __shared__ float Bs[8][128];
    const int tid  = threadIdx.x;
    const int brow = blockIdx.y, bcol = blockIdx.x;
    const int tr = tid >> 4, tc = tid & 15;
    const int aRow = tid >> 1, aCol = (tid & 1) * 4;
    const int bRow = tid >> 5, bCol = (tid & 31) * 4;
    const float* Ap = A + (size_t)(brow * 128) * K;
    const float* Bp = Bm + bcol * 128;

    float acc[8][8];
#pragma unroll
    for (int i = 0; i < 8; i++)
#pragma unroll
        for (int j = 0; j < 8; j++) acc[i][j] = 0.f;

    for (int k0 = 0; k0 < K; k0 += 8) {
        float4 av = *(const float4*)(Ap + (size_t)aRow * K + k0 + aCol);
        As[aCol + 0][aRow] = av.x; As[aCol + 1][aRow] = av.y;
        As[aCol + 2][aRow] = av.z; As[aCol + 3][aRow] = av.w;
        float4 bv = *(const float4*)(Bp + (size_t)(k0 + bRow) * N + bCol);
        *(float4*)&Bs[bRow][bCol] = bv;
        __syncthreads();
#pragma unroll
        for (int kk = 0; kk < 8; kk++) {
            float4 a0 = *(const float4*)&As[kk][tr * 8];
            float4 a1 = *(const float4*)&As[kk][tr * 8 + 4];
            float4 b0 = *(const float4*)&Bs[kk][tc * 8];
            float4 b1 = *(const float4*)&Bs[kk][tc * 8 + 4];
            float ar[8] = {a0.x,a0.y,a0.z,a0.w,a1.x,a1.y,a1.z,a1.w};
            float br[8] = {b0.x,b0.y,b0.z,b0.w,b1.x,b1.y,b1.z,b1.w};
#pragma unroll
            for (int i = 0; i < 8; i++)
#pragma unroll
                for (int j = 0; j < 8; j++)
                    acc[i][j] = fmaf(ar[i], br[j], acc[i][j]);
        }
        __syncthreads();
    }
#pragma unroll
    for (int i = 0; i < 8; i++) {
        int row = brow * 128 + tr * 8 + i;
#pragma unroll
        for (int j = 0; j < 8; j += 2) {
            int col = bcol * 128 + tc * 8 + j;
            float v0 = fmaxf(acc[i][j]     + bias[col],     0.f);
            float v1 = fmaxf(acc[i][j + 1] + bias[col + 1], 0.f);
            pack_a(g_h1pk, row, col, v0, v1);
        }
    }
}

// ---------------- pack weights into split B-fragment layout ----------------
__global__ void pack_weights(const float* __restrict__ W1, const float* __restrict__ Wr,
                             const float* __restrict__ Wk, const float* __restrict__ We2,
                             const float* __restrict__ W2)
{
    const int TOT1 = (N1 / 8) * 64 * 32;
    const int TOT2 = (N2 / 8) * 64 * 32;
    const int TOT3 = (UU / 8) * 64 * 32;
    int c = blockIdx.x * blockDim.x + threadIdx.x;
    float w[4];
    __nv_bfloat16* o;
    if (c < TOT1) {
        int cl = c;
        int nt8 = cl / 2048, rem = cl % 2048, kt = rem >> 5, l = rem & 31;
        int n  = nt8 * 8 + (l >> 2);
        int k0 = kt * 16 + (l & 3) * 2;
        const float* W; int ld, nn;
        if (n < 1024) { W = W1; ld = 1024; nn = n; }
        else          { W = Wr; ld = 4096; nn = n - 1024; }
        w[0] = W[(size_t)(k0    ) * ld + nn];
        w[1] = W[(size_t)(k0 + 1) * ld + nn];
        w[2] = W[(size_t)(k0 + 8) * ld + nn];
        w[3] = W[(size_t)(k0 + 9) * ld + nn];
        o = g_Wpk1 + (size_t)cl * 8;
    } else if (c < TOT1 + TOT2) {
        int cl = c - TOT1;
        int nt8 = cl / 2048, rem = cl % 2048, kt = rem >> 5, l = rem & 31;
        int n  = nt8 * 8 + (l >> 2);
        int k0 = kt * 16 + (l & 3) * 2;
        w[0] = Wk[(size_t)(k0    ) * 4096 + n];
        w[1] = Wk[(size_t)(k0 + 1) * 4096 + n];
        w[2] = Wk[(size_t)(k0 + 8) * 4096 + n];
        w[3] = Wk[(size_t)(k0 + 9) * 4096 + n];
        o = g_Wpk2 + (size_t)cl * 8;
    } else if (c < TOT1 + TOT2 + 2 * TOT3) {
        int cl = c - TOT1 - TOT2;
        const float* W = We2;
        __nv_bfloat16* dst = g_We2pk;
        if (cl >= TOT3) { cl -= TOT3; W = W2; dst = g_W2pk; }
        int nt8 = cl / 2048, rem = cl % 2048, kt = rem >> 5, l = rem & 31;
        int n  = nt8 * 8 + (l >> 2);
        int k0 = kt * 16 + (l & 3) * 2;
        w[0] = W[(size_t)(k0    ) * 1024 + n];
        w[1] = W[(size_t)(k0 + 1) * 1024 + n];
        w[2] = W[(size_t)(k0 + 8) * 1024 + n];
        w[3] = W[(size_t)(k0 + 9) * 1024 + n];
        o = dst + (size_t)cl * 8;
    } else return;
#pragma unroll
    for (int i = 0; i < 4; i++) split_bf16(w[i], o[i], o[4 + i]);
}

// ---------------- big split-bf16 HMMA (precompute) ----------------
__global__ __launch_bounds__(256)
void hgemm_big(const __nv_bfloat16* __restrict__ Apk,
               const __nv_bfloat16* __restrict__ Wpk,
               const float* __restrict__ bias, int doRelu, int N,
               __nv_bfloat16* __restrict__ outPk, __half* __restrict__ outH)
{
    const int tiles_n = N / 32;
    const int tm = blockIdx.x / tiles_n, tn = blockIdx.x % tiles_n;
    const int tid = threadIdx.x;
    const int w = tid >> 5, l = tid & 31;
    const int mt = w >> 1, np = w & 1;
    const int mtg = tm * 4 + mt;
    const uint4* a_it  = (const uint4*)Apk + ((size_t)mtg * 2048 + l) * 2;
    const int nt0 = tn * 4 + np * 2;
    const uint4* b0_it = (const uint4*)Wpk + (size_t)nt0 * 2048 + l;
    const uint4* b1_it = b0_it + 2048;

    float d0[4] = {0.f,0.f,0.f,0.f};
    float d1[4] = {0.f,0.f,0.f,0.f};
#pragma unroll 4
    for (int kt = 0; kt < 64; kt++) {
        uint4 aH = a_it[(size_t)kt * 64];
        uint4 aL = a_it[(size_t)kt * 64 + 1];
        uint4 b0 = b0_it[kt * 32];
        uint4 b1 = b1_it[kt * 32];
        uint2 b0H = make_uint2(b0.x, b0.y), b0L = make_uint2(b0.z, b0.w);
        uint2 b1H = make_uint2(b1.x, b1.y), b1L = make_uint2(b1.z, b1.w);
        mma16816(d0, aH, b0H);
        mma16816(d0, aH, b0L);
        mma16816(d0, aL, b0H);
        mma16816(d1, aH, b1H);
        mma16816(d1, aH, b1L);
        mma16816(d1, aL, b1H);
    }
    const int r0 = tm * 64 + mt * 16 + (l >> 2);
    const int c0 = tn * 32 + np * 16 + ((l & 3) << 1);
    float2 bbA = *(const float2*)&bias[c0];
    float2 bbB = *(const float2*)&bias[c0 + 8];
    d0[0] += bbA.x; d0[1] += bbA.y; d0[2] += bbA.x; d0[3] += bbA.y;
    d1[0] += bbB.x; d1[1] += bbB.y; d1[2] += bbB.x; d1[3] += bbB.y;
    if (doRelu) {
#pragma unroll
        for (int i = 0; i < 4; i++) {
            d0[i] = fmaxf(d0[i], 0.f);
            d1[i] = fmaxf(d1[i], 0.f);
        }
    }
    if (outH) {
        *(__half2*)&outH[(size_t)r0 * N + c0]           = __floats2half2_rn(d0[0], d0[1]);
        *(__half2*)&outH[(size_t)(r0 + 8) * N + c0]     = __floats2half2_rn(d0[2], d0[3]);
        *(__half2*)&outH[(size_t)r0 * N + c0 + 8]       = __floats2half2_rn(d1[0], d1[1]);
        *(__half2*)&outH[(size_t)(r0 + 8) * N + c0 + 8] = __floats2half2_rn(d1[2], d1[3]);
    }
    if (outPk) {
        pack_a(outPk, r0,     c0,     d0[0], d0[1]);
        pack_a(outPk, r0 + 8, c0,     d0[2], d0[3]);
        pack_a(outPk, r0,     c0 + 8, d1[0], d1[1]);
        pack_a(outPk, r0 + 8, c0 + 8, d1[2], d1[3]);
    }
}

// ---------------- init ----------------
__global__ void init_state(float* __restrict__ out)
{
    int idx = blockIdx.x * blockDim.x + threadIdx.x;
    if (idx < BB * UU) {
        g_c[idx] = 0.f;
        g_hpk[idx] = __float2bfloat16(0.f);
        g_hpk[BB * UU + idx] = __float2bfloat16(0.f);
    }
    if (idx < SEQ * BB) out[idx] = 0.f;
    if (idx < BB * 32) g_pair[idx] = 0;
    if (idx < 2 * 32) { g_ctxc[idx] = 0; g_hcnt[idx] = 0; }
    if (idx == 0) { g_bar_cnt = 0; g_qcnt = 0; }
}

// ---------------- smem-staged 64xN step-GEMM task (split-K half) ----------
template<int NJ>
__device__ __forceinline__ void gtile(const uint4* __restrict__ Apk,
                                      const uint4* __restrict__ Wpk,
                                      float* __restrict__ C, int ldc,
                                      int n0, int khalf,
                                      uint4* sA, uint4* sB)
{
    constexpr int NT = 2 * NJ;
    const int tid = threadIdx.x;
    const int w = tid >> 5, l = tid & 31;
    const int mt = w >> 1, np = w & 1;
    const int nt8base = n0 >> 3;
    const int ktbase = khalf * 32;

    float d[NJ][4];
#pragma unroll
    for (int j = 0; j < NJ; j++)
#pragma unroll
        for (int i = 0; i < 4; i++) d[j][i] = 0.f;

    auto load = [&](int buf, int cix) {
        const int kt0 = ktbase + cix * 8;
#pragma unroll
        for (int i = tid; i < 1024; i += 256) {
            int lane = i & 31, mtt = (i >> 5) & 3, ktl = i >> 7;
            const uint4* src = Apk + ((size_t)(mtt * 64 + kt0 + ktl) * 32 + lane) * 2;
            cp16(&sA[(((buf * 2 + 0) * 8 + ktl) * 4 + mtt) * 32 + lane], src);
            cp16(&sA[(((buf * 2 + 1) * 8 + ktl) * 4 + mtt) * 32 + lane], src + 1);
        }
        for (int i = tid; i < NT * 8 * 32; i += 256) {
            int lane = i & 31, nt = (i >> 5) % NT, ktl = (i >> 5) / NT;
            const uint4* src = Wpk + (size_t)((nt8base + nt) * 64 + kt0 + ktl) * 32 + lane;
            cp16(&sB[((buf * 8 + ktl) * NT + nt) * 32 + lane], src);
        }
        cp_commit();
    };

    load(0, 0);
    for (int c = 0; c < 4; c++) {
        if (c < 3) { load((c + 1) & 1, c + 1); cp_wait<1>(); }
        else       { cp_wait<0>(); }
        __syncthreads();
        const int buf = c & 1;
#pragma unroll
        for (int ktl = 0; ktl < 8; ktl++) {
            uint4 aH = sA[(((buf * 2 + 0) * 8 + ktl) * 4 + mt) * 32 + l];
            uint4 aL = sA[(((buf * 2 + 1) * 8 + ktl) * 4 + mt) * 32 + l];
#pragma unroll
            for (int j = 0; j < NJ; j++) {
                uint4 b = sB[((buf * 8 + ktl) * NT + np * NJ + j) * 32 + l];
                uint2 bH = make_uint2(b.x, b.y), bL = make_uint2(b.z, b.w);
                mma16816(d[j], aH, bH);
                mma16816(d[j], aH, bL);
                mma16816(d[j], aL, bH);
            }
        }
        __syncthreads();
    }
    const int r0 = mt * 16 + (l >> 2);
#pragma unroll
    for (int j = 0; j < NJ; j++) {
        const int c0 = n0 + (np * NJ + j) * 8 + ((l & 3) << 1);
        *(float2*)&C[(size_t)r0 * ldc + c0]       = make_float2(d[j][0], d[j][1]);
        *(float2*)&C[(size_t)(r0 + 8) * ldc + c0] = make_float2(d[j][2], d[j][3]);
    }
}

// ---------------- persistent decode (1 full bar + 4 narrow waits / step) ----
extern __shared__ uint4 dynsm[];
__global__ __launch_bounds__(256, 1)
void decode_persistent(const float* __restrict__ b1, const float* __restrict__ V,
                       const float* __restrict__ bl, const float* __restrict__ Wo,
                       const float* __restrict__ bo, float* __restrict__ out)
{
    __shared__ float sm[256];
    __shared__ float red[8];
    uint4* sA = dynsm;          // 64 KB
    uint4* sB = dynsm + 4096;   // 80 KB
    const int tid  = threadIdx.x;
    const int bid  = blockIdx.x;
    const int warp = tid >> 5, lane = tid & 31;
    const int bh   = bid & 1;   // block half-index (kh in P1/P4, thalf/uhalf/jhalf)

    const uint4* hpk_u4  = (const uint4*)g_hpk;
    const uint4* cpk_u4  = (const uint4*)g_cpk;
    const uint4* wpk1_u4 = (const uint4*)g_Wpk1;
    const uint4* wpk2_u4 = (const uint4*)g_Wpk2;

    for (int s = 0; s < SEQ; s++) {
        const int par = s & 1;
        float (*qp)[BB][N1] = g_qp[par];
        float* sc = g_sc[par];

        // ---- wait: h of matching half from prev step's P5 ----
        ctr_wait(&g_hcnt[bh * 32], 64u * (unsigned)s);

        // ---- phase 1: qp[kh] = h @ [W1|Wr]; q-tiles first + release flag ----
        {
            int tile, kh;
            if (bid < 26) { tile = bid >> 1;            kh = bid & 1; }
            else          { int t = bid - 26; tile = 13 + (t >> 1); kh = t & 1; }
            gtile<5>(hpk_u4, wpk1_u4, &qp[kh][0][0], N1, tile * 80, kh, sA, sB);
            if (bid < 26) ctr_release(&g_qcnt);
        }
        ctr_wait(&g_qcnt, 26u * (unsigned)(s + 1));

        // ---- phase 2: scores for (b, thalf) ----
        const int b2s = bid >> 1;
        {
            const int b = b2s, thalf = bh;
            float qr[32], vr[32];
#pragma unroll
            for (int it = 0; it < 4; it++) {
                const int base = it * 256 + lane * 8;
#pragma unroll
                for (int k2 = 0; k2 < 8; k2 += 4) {
                    float4 q0 = *(const float4*)&qp[0][b][base + k2];
                    float4 q1 = *(const float4*)&qp[1][b][base + k2];
                    float4 bb = *(const float4*)&b1[base + k2];
                    float4 vv = *(const float4*)&V[base + k2];
                    qr[it*8+k2+0] = q0.x + q1.x + bb.x;  vr[it*8+k2+0] = vv.x;
                    qr[it*8+k2+1] = q0.y + q1.y + bb.y;  vr[it*8+k2+1] = vv.y;
                    qr[it*8+k2+2] = q0.z + q1.z + bb.z;  vr[it*8+k2+2] = vv.z;
                    qr[it*8+k2+3] = q0.w + q1.w + bb.w;  vr[it*8+k2+3] = vv.w;
                }
            }
            for (int t = warp; t < 128; t += 8) {
                const int tt = thalf * 128 + t;
                const uint4* kp = (const uint4*)(g_keh + ((size_t)(b * 256 + tt)) * 1024);
                float s0 = 0.f;
#pragma unroll
                for (int it = 0; it < 4; it++) {
                    uint4 kv = kp[it * 32 + lane];
                    float2 f0 = __half22float2(*(__half2*)&kv.x);
                    float2 f1 = __half22float2(*(__half2*)&kv.y);
                    float2 f2 = __half22float2(*(__half2*)&kv.z);
                    float2 f3 = __half22float2(*(__half2*)&kv.w);
                    s0 += vr[it*8+0] * tanh_hw(qr[it*8+0] + f0.x);
                    s0 += vr[it*8+1] * tanh_hw(qr[it*8+1] + f0.y);
                    s0 += vr[it*8+2] * tanh_hw(qr[it*8+2] + f1.x);
                    s0 += vr[it*8+3] * tanh_hw(qr[it*8+3] + f1.y);
                    s0 += vr[it*8+4] * tanh_hw(qr[it*8+4] + f2.x);
                    s0 += vr[it*8+5] * tanh_hw(qr[it*8+5] + f2.y);
                    s0 += vr[it*8+6] * tanh_hw(qr[it*8+6] + f3.x);
                    s0 += vr[it*8+7] * tanh_hw(qr[it*8+7] + f3.y);
                }
#pragma unroll
                for (int o = 16; o; o >>= 1) s0 += __shfl_xor_sync(0xffffffffu, s0, o);
                if (!lane) sc[b * 256 + tt] = s0;
            }
        }
        // pairwise sync: blocks (2b, 2b+1) exchange score halves
        {
            __syncthreads();
            if (tid == 0) {
                unsigned d;
                asm volatile("atom.add.release.gpu.u32 %0, [%1], 1;"
                             : "=r"(d) : "l"(&g_pair[b2s * 32]));
                const unsigned tgt = 2u * (unsigned)(s + 1);
                unsigned g;
                do {
                    asm volatile("ld.acquire.gpu.u32 %0, [%1];"
                                 : "=r"(g) : "l"(&g_pair[b2s * 32]));
                } while (g < tgt);
            }
            __syncthreads();
        }

        // ---- phase 3: softmax (redundant in pair) + ctx for (b, uhalf) ----
        {
            const int b = b2s, uhalf = bh;
            float v = sc[b * 256 + tid];
            float m = v;
#pragma unroll
            for (int o = 16; o; o >>= 1) m = fmaxf(m, __shfl_xor_sync(0xffffffffu, m, o));
            if (!lane) red[warp] = m;
            __syncthreads();
            float bm = red[0];
#pragma unroll
            for (int w2 = 1; w2 < 8; w2++) bm = fmaxf(bm, red[w2]);
            __syncthreads();
            float e = __expf(v - bm);
            float ss = e;
#pragma unroll
            for (int o = 16; o; o >>= 1) ss += __shfl_xor_sync(0xffffffffu, ss, o);
            if (!lane) red[warp] = ss;
            __syncthreads();
            float bs = 0.f;
#pragma unroll
            for (int w2 = 0; w2 < 8; w2++) bs += red[w2];
            sm[tid] = __fdividef(e, bs);
            __syncthreads();

            const int u0 = uhalf * 512 + tid * 2;
            const __half2* xb = (const __half2*)(g_xh + (size_t)b * 256 * 1024 + u0);
            float ax = 0.f, ay = 0.f;
#pragma unroll 8
            for (int t = 0; t < 256; t++) {
                float2 xv = __half22float2(xb[(size_t)t * 512]);
                float wt = sm[t];
                ax = fmaf(wt, xv.x, ax);
                ay = fmaf(wt, xv.y, ay);
            }
            pack_a(g_cpk, b, u0, ax, ay);
        }
        ctr_release(&g_ctxc[bh * 32]);                  // ctx half published

        // ---- phase 4: zp[kh] = ctx @ Wk; wait only matching ctx half ----
        {
            const int tile = bid & 63, kh = bid >> 6;
            ctr_wait(&g_ctxc[kh * 32], 64u * (unsigned)(s + 1));
            gtile<4>(cpk_u4, wpk2_u4, &g_zp[kh][0][0], N2, tile * 64, kh, sA, sB);
        }
        grid_bar();   // publishes zp AND hr (program order) to everyone

        // ---- phase 5: LSTM gates + state + projection for (b2, jhalf) ----
        {
            const int b2 = b2s, jhalf = bh;
            const int j0 = jhalf * 512 + tid * 2;
            const float* z0 = g_zp[0][b2]; const float* z1 = g_zp[1][b2];
            const float* h0 = qp[0][b2] + 1024; const float* h1 = qp[1][b2] + 1024;
            float2 a0, a1, c0, c1;
            a0 = *(const float2*)&z0[j0];        a1 = *(const float2*)&z1[j0];
            c0 = *(const float2*)&h0[j0];        c1 = *(const float2*)&h1[j0];
            float2 zi = { bl[j0]   + a0.x + a1.x + c0.x + c1.x,
                          bl[j0+1] + a0.y + a1.y + c0.y + c1.y };
            a0 = *(const float2*)&z0[1024+j0];   a1 = *(const float2*)&z1[1024+j0];
            c0 = *(const float2*)&h0[1024+j0];   c1 = *(const float2*)&h1[1024+j0];
            float2 zf = { bl[1024+j0]   + a0.x + a1.x + c0.x + c1.x,
                          bl[1024+j0+1] + a0.y + a1.y + c0.y + c1.y };
            a0 = *(const float2*)&z0[2048+j0];   a1 = *(const float2*)&z1[2048+j0];
            c0 = *(const float2*)&h0[2048+j0];   c1 = *(const float2*)&h1[2048+j0];
            float2 zg = { bl[2048+j0]   + a0.x + a1.x + c0.x + c1.x,
                          bl[2048+j0+1] + a0.y + a1.y + c0.y + c1.y };
            a0 = *(const float2*)&z0[3072+j0];   a1 = *(const float2*)&z1[3072+j0];
            c0 = *(const float2*)&h0[3072+j0];   c1 = *(const float2*)&h1[3072+j0];
            float2 zo = { bl[3072+j0]   + a0.x + a1.x + c0.x + c1.x,
                          bl[3072+j0+1] + a0.y + a1.y + c0.y + c1.y };

            float2 cold = *(const float2*)&g_c[b2 * 1024 + j0];
            float cx = sigf(zf.x) * cold.x + sigf(zi.x) * fast_tanh(zg.x);
            float cy = sigf(zf.y) * cold.y + sigf(zi.y) * fast_tanh(zg.y);
            float hx = sigf(zo.x) * fast_tanh(cx);
            float hy = sigf(zo.y) * fast_tanh(cy);
            *(float2*)&g_c[b2 * 1024 + j0] = make_float2(cx, cy);
            pack_a(g_hpk, b2, j0, hx, hy);

            float p = hx * Wo[j0] + hy * Wo[j0 + 1];
            if (tid == 0 && jhalf == 0) p += bo[0];
#pragma unroll
            for (int o = 16; o; o >>= 1) p += __shfl_xor_sync(0xffffffffu, p, o);
            if (!lane) red[warp] = p;
            __syncthreads();
            if (tid == 0) {
                float acc = 0.f;
#pragma unroll
                for (int w2 = 0; w2 < 8; w2++) acc += red[w2];
                atomicAdd(&out[s * 64 + b2], acc);
            }
        }
        ctr_release(&g_hcnt[bh * 32]);                  // h half published
    }
}

// ---------------- host launcher ----------------
extern "C" void kernel_launch(void* const* d_in, const int* in_sizes, int n_in,
                              void* d_out, int out_size)
{
    const float* inputs = (const float*)d_in[0];
    const float* We1 = (const float*)d_in[1];  const float* be1 = (const float*)d_in[2];
    const float* We2 = (const float*)d_in[3];  const float* be2 = (const float*)d_in[4];
    const float* W1  = (const float*)d_in[5];  const float* b1  = (const float*)d_in[6];
    const float* W2  = (const float*)d_in[7];  const float* b2k = (const float*)d_in[8];
    const float* V   = (const float*)d_in[9];  /* bV shift-invariant in softmax */
    const float* Wk  = (const float*)d_in[11]; const float* Wr  = (const float*)d_in[12];
    const float* bl  = (const float*)d_in[13]; const float* Wo  = (const float*)d_in[14];
    const float* bo  = (const float*)d_in[15];
    float* out = (float*)d_out;

    void *p_h1pk, *p_xpk, *p_xh, *p_keh, *p_We2pk, *p_W2pk;
    cudaGetSymbolAddress(&p_h1pk,  g_h1pk);
    cudaGetSymbolAddress(&p_xpk,   g_xpk);
    cudaGetSymbolAddress(&p_xh,    g_xh);
    cudaGetSymbolAddress(&p_keh,   g_keh);
    cudaGetSymbolAddress(&p_We2pk, g_We2pk);
    cudaGetSymbolAddress(&p_W2pk,  g_W2pk);

    const int DYN_SMEM = (4096 + 5120) * 16;   // 144 KB
    static int attr_set = 0;
    if (!attr_set) {
        cudaFuncSetAttribute(decode_persistent,
                             cudaFuncAttributeMaxDynamicSharedMemorySize, DYN_SMEM);
        attr_set = 1;
    }

    pack_weights<<<5632, 512>>>(W1, Wr, Wk, We2, W2);
    sgemm128_pack<<<dim3(UU / 128, NROW / 128), 256>>>(inputs, We1, be1, UU, DINN);
    hgemm_big<<<(NROW / 64) * (UU / 32), 256>>>(
        (const __nv_bfloat16*)p_h1pk, (const __nv_bfloat16*)p_We2pk, be2, 1, UU,
        (__nv_bfloat16*)p_xpk, (__half*)p_xh);
    hgemm_big<<<(NROW / 64) * (UU / 32), 256>>>(
        (const __nv_bfloat16*)p_xpk, (const __nv_bfloat16*)p_W2pk, b2k, 0, UU,
        (__nv_bfloat16*)0, (__half*)p_keh);
    init_state<<<64, 1024>>>(out);
    decode_persistent<<<NB, 256, DYN_SMEM>>>(b1, V, bl, Wo, bo, out);
}